// round 1
// baseline (speedup 1.0000x reference)
#include <cuda_runtime.h>

// SNN: 20-step LIF network, feedback loop s2 -> layer1.
// Round 1: fp32 SIMT tiled GEMM with fused LIF epilogue (correct baseline).

namespace {
constexpr int Bq  = 4096;   // batch
constexpr int D   = 1024;   // input dim
constexpr int H1n = 2048;
constexpr int H2n = 1024;
constexpr int Cn  = 64;
constexpr int NSTEPS = 20;
constexpr float BETA = 0.9f;
constexpr float THR  = 1.0f;
}

// Persistent state / scratch (allocation-free per harness rules)
__device__ float g_mem1[(size_t)Bq * H1n];
__device__ float g_s1  [(size_t)Bq * H1n];
__device__ float g_mem2[(size_t)Bq * H2n];
__device__ float g_s2  [(size_t)Bq * H2n];
__device__ float g_spk [(size_t)Bq * H2n];

__global__ void zero_kernel() {
    size_t i = (size_t)blockIdx.x * blockDim.x + threadIdx.x;
    size_t stride = (size_t)gridDim.x * blockDim.x;
    const float4 z = make_float4(0.f, 0.f, 0.f, 0.f);
    for (size_t j = i; j < (size_t)Bq * H1n / 4; j += stride)
        reinterpret_cast<float4*>(g_mem1)[j] = z;
    for (size_t j = i; j < (size_t)Bq * H2n / 4; j += stride) {
        reinterpret_cast<float4*>(g_mem2)[j] = z;
        reinterpret_cast<float4*>(g_spk )[j] = z;
    }
}

// C[m,n] = A[m,:] . W[n,:]  (A: [M,K] row-major, W: [N,K] row-major)
// fused epilogue: mem' = BETA*mem + (C + bias) - THR*(mem>THR); s = (mem'>THR)
template<int LAYER>
__global__ __launch_bounds__(256, 2) void gemm_step(
    const float* __restrict__ Xin,
    const float* __restrict__ W,
    const float* __restrict__ bias,
    int use_x)
{
    constexpr int K = (LAYER == 1) ? D   : H1n;
    constexpr int N = (LAYER == 1) ? H1n : H2n;

    const float* A   = (LAYER == 1) ? (use_x ? Xin : g_s2) : g_s1;
    float* mem  = (LAYER == 1) ? g_mem1 : g_mem2;
    float* sout = (LAYER == 1) ? g_s1   : g_s2;

    const int m0 = blockIdx.y * 128;
    const int n0 = blockIdx.x * 128;
    const int tid = threadIdx.x;
    const int tx = tid & 15;
    const int ty = tid >> 4;

    __shared__ float As[8][128];
    __shared__ float Bs[8][128];

    float acc[8][8];
    #pragma unroll
    for (int i = 0; i < 8; i++)
        #pragma unroll
        for (int j = 0; j < 8; j++) acc[i][j] = 0.f;

    const int ldRow = tid >> 1;          // 0..127
    const int ldCol = (tid & 1) * 4;     // 0 or 4
    const float* Ap = A + (size_t)(m0 + ldRow) * K + ldCol;
    const float* Wp = W + (size_t)(n0 + ldRow) * K + ldCol;

    for (int k0 = 0; k0 < K; k0 += 8) {
        float4 a4 = *reinterpret_cast<const float4*>(Ap + k0);
        float4 b4 = *reinterpret_cast<const float4*>(Wp + k0);
        As[ldCol + 0][ldRow] = a4.x;
        As[ldCol + 1][ldRow] = a4.y;
        As[ldCol + 2][ldRow] = a4.z;
        As[ldCol + 3][ldRow] = a4.w;
        Bs[ldCol + 0][ldRow] = b4.x;
        Bs[ldCol + 1][ldRow] = b4.y;
        Bs[ldCol + 2][ldRow] = b4.z;
        Bs[ldCol + 3][ldRow] = b4.w;
        __syncthreads();

        #pragma unroll
        for (int kk = 0; kk < 8; kk++) {
            float ar[8], br[8];
            *reinterpret_cast<float4*>(ar)     = *reinterpret_cast<const float4*>(&As[kk][ty * 8]);
            *reinterpret_cast<float4*>(ar + 4) = *reinterpret_cast<const float4*>(&As[kk][ty * 8 + 4]);
            *reinterpret_cast<float4*>(br)     = *reinterpret_cast<const float4*>(&Bs[kk][tx * 8]);
            *reinterpret_cast<float4*>(br + 4) = *reinterpret_cast<const float4*>(&Bs[kk][tx * 8 + 4]);
            #pragma unroll
            for (int i = 0; i < 8; i++)
                #pragma unroll
                for (int j = 0; j < 8; j++)
                    acc[i][j] = fmaf(ar[i], br[j], acc[i][j]);
        }
        __syncthreads();
    }

    // Fused LIF epilogue
    float bl[8];
    #pragma unroll
    for (int j = 0; j < 8; j++) bl[j] = bias[n0 + tx * 8 + j];

    #pragma unroll
    for (int i = 0; i < 8; i++) {
        int r = m0 + ty * 8 + i;
        size_t base = (size_t)r * N + n0 + tx * 8;
        #pragma unroll
        for (int v = 0; v < 2; v++) {
            float4 m4 = *reinterpret_cast<float4*>(&mem[base + v * 4]);
            float* mv = &m4.x;
            float sv[4];
            #pragma unroll
            for (int q = 0; q < 4; q++) {
                float h  = acc[i][v * 4 + q] + bl[v * 4 + q];
                float mo = mv[q];
                float mn = BETA * mo + h - ((mo > THR) ? THR : 0.f);
                mv[q] = mn;
                sv[q] = (mn > THR) ? 1.f : 0.f;
            }
            *reinterpret_cast<float4*>(&mem[base + v * 4]) = m4;
            *reinterpret_cast<float4*>(&sout[base + v * 4]) =
                make_float4(sv[0], sv[1], sv[2], sv[3]);
            if (LAYER == 2) {
                float4 p = *reinterpret_cast<float4*>(&g_spk[base + v * 4]);
                p.x += sv[0]; p.y += sv[1]; p.z += sv[2]; p.w += sv[3];
                *reinterpret_cast<float4*>(&g_spk[base + v * 4]) = p;
            }
        }
    }
}

// out[b,c] = (spk_sum[b,:]/NSTEPS) . Wo[c,:] + bo[c]
__global__ __launch_bounds__(256) void out_kernel(
    const float* __restrict__ Wo,
    const float* __restrict__ bo,
    float* __restrict__ out)
{
    __shared__ float wsh[64 * 129];
    const int tid = threadIdx.x;
    const int c  = tid & 63;
    const int rr = tid >> 6;              // 0..3
    const int b  = blockIdx.x * 4 + rr;

    float acc = 0.f;
    for (int k0 = 0; k0 < H2n; k0 += 128) {
        __syncthreads();
        #pragma unroll
        for (int it = 0; it < 8; it++) {
            int l  = tid + it * 256;      // 0..2047
            int c2 = l >> 5;              // 0..63
            int kk = (l & 31) * 4;        // 0..124
            float4 w4 = *reinterpret_cast<const float4*>(&Wo[(size_t)c2 * H2n + k0 + kk]);
            wsh[c2 * 129 + kk + 0] = w4.x;
            wsh[c2 * 129 + kk + 1] = w4.y;
            wsh[c2 * 129 + kk + 2] = w4.z;
            wsh[c2 * 129 + kk + 3] = w4.w;
        }
        __syncthreads();
        const float* sp = &g_spk[(size_t)b * H2n + k0];
        #pragma unroll
        for (int k = 0; k < 128; k += 4) {
            float4 s4 = *reinterpret_cast<const float4*>(sp + k);
            acc = fmaf(s4.x, wsh[c * 129 + k + 0], acc);
            acc = fmaf(s4.y, wsh[c * 129 + k + 1], acc);
            acc = fmaf(s4.z, wsh[c * 129 + k + 2], acc);
            acc = fmaf(s4.w, wsh[c * 129 + k + 3], acc);
        }
    }
    out[(size_t)b * Cn + c] = acc * (1.0f / NSTEPS) + bo[c];
}

extern "C" void kernel_launch(void* const* d_in, const int* in_sizes, int n_in,
                              void* d_out, int out_size)
{
    const float* x  = (const float*)d_in[0];
    const float* W1 = (const float*)d_in[1];
    const float* b1 = (const float*)d_in[2];
    const float* W2 = (const float*)d_in[3];
    const float* b2 = (const float*)d_in[4];
    const float* Wo = (const float*)d_in[5];
    const float* bo = (const float*)d_in[6];
    float* out = (float*)d_out;

    zero_kernel<<<512, 256>>>();

    dim3 blk(256);
    dim3 g1(H1n / 128, Bq / 128);
    dim3 g2(H2n / 128, Bq / 128);
    for (int t = 0; t < NSTEPS; t++) {
        gemm_step<1><<<g1, blk>>>(x, W1, b1, (t == 0) ? 1 : 0);
        gemm_step<2><<<g2, blk>>>(x, W2, b2, 0);
    }
    out_kernel<<<Bq / 4, 256>>>(Wo, bo, out);
}

// round 2
// speedup vs baseline: 1.0007x; 1.0007x over previous
#include <cuda_runtime.h>

// SNN: 20-step LIF network, feedback loop s2 -> layer1.
// Round 1: fp32 SIMT tiled GEMM with fused LIF epilogue (correct baseline).

namespace {
constexpr int Bq  = 4096;   // batch
constexpr int D   = 1024;   // input dim
constexpr int H1n = 2048;
constexpr int H2n = 1024;
constexpr int Cn  = 64;
constexpr int NSTEPS = 20;
constexpr float BETA = 0.9f;
constexpr float THR  = 1.0f;
}

// Persistent state / scratch (allocation-free per harness rules)
__device__ float g_mem1[(size_t)Bq * H1n];
__device__ float g_s1  [(size_t)Bq * H1n];
__device__ float g_mem2[(size_t)Bq * H2n];
__device__ float g_s2  [(size_t)Bq * H2n];
__device__ float g_spk [(size_t)Bq * H2n];

__global__ void zero_kernel() {
    size_t i = (size_t)blockIdx.x * blockDim.x + threadIdx.x;
    size_t stride = (size_t)gridDim.x * blockDim.x;
    const float4 z = make_float4(0.f, 0.f, 0.f, 0.f);
    for (size_t j = i; j < (size_t)Bq * H1n / 4; j += stride)
        reinterpret_cast<float4*>(g_mem1)[j] = z;
    for (size_t j = i; j < (size_t)Bq * H2n / 4; j += stride) {
        reinterpret_cast<float4*>(g_mem2)[j] = z;
        reinterpret_cast<float4*>(g_spk )[j] = z;
    }
}

// C[m,n] = A[m,:] . W[n,:]  (A: [M,K] row-major, W: [N,K] row-major)
// fused epilogue: mem' = BETA*mem + (C + bias) - THR*(mem>THR); s = (mem'>THR)
template<int LAYER>
__global__ __launch_bounds__(256, 2) void gemm_step(
    const float* __restrict__ Xin,
    const float* __restrict__ W,
    const float* __restrict__ bias,
    int use_x)
{
    constexpr int K = (LAYER == 1) ? D   : H1n;
    constexpr int N = (LAYER == 1) ? H1n : H2n;

    const float* A   = (LAYER == 1) ? (use_x ? Xin : g_s2) : g_s1;
    float* mem  = (LAYER == 1) ? g_mem1 : g_mem2;
    float* sout = (LAYER == 1) ? g_s1   : g_s2;

    const int m0 = blockIdx.y * 128;
    const int n0 = blockIdx.x * 128;
    const int tid = threadIdx.x;
    const int tx = tid & 15;
    const int ty = tid >> 4;

    __shared__ float As[8][128];
    __shared__ float Bs[8][128];

    float acc[8][8];
    #pragma unroll
    for (int i = 0; i < 8; i++)
        #pragma unroll
        for (int j = 0; j < 8; j++) acc[i][j] = 0.f;

    const int ldRow = tid >> 1;          // 0..127
    const int ldCol = (tid & 1) * 4;     // 0 or 4
    const float* Ap = A + (size_t)(m0 + ldRow) * K + ldCol;
    const float* Wp = W + (size_t)(n0 + ldRow) * K + ldCol;

    for (int k0 = 0; k0 < K; k0 += 8) {
        float4 a4 = *reinterpret_cast<const float4*>(Ap + k0);
        float4 b4 = *reinterpret_cast<const float4*>(Wp + k0);
        As[ldCol + 0][ldRow] = a4.x;
        As[ldCol + 1][ldRow] = a4.y;
        As[ldCol + 2][ldRow] = a4.z;
        As[ldCol + 3][ldRow] = a4.w;
        Bs[ldCol + 0][ldRow] = b4.x;
        Bs[ldCol + 1][ldRow] = b4.y;
        Bs[ldCol + 2][ldRow] = b4.z;
        Bs[ldCol + 3][ldRow] = b4.w;
        __syncthreads();

        #pragma unroll
        for (int kk = 0; kk < 8; kk++) {
            float ar[8], br[8];
            *reinterpret_cast<float4*>(ar)     = *reinterpret_cast<const float4*>(&As[kk][ty * 8]);
            *reinterpret_cast<float4*>(ar + 4) = *reinterpret_cast<const float4*>(&As[kk][ty * 8 + 4]);
            *reinterpret_cast<float4*>(br)     = *reinterpret_cast<const float4*>(&Bs[kk][tx * 8]);
            *reinterpret_cast<float4*>(br + 4) = *reinterpret_cast<const float4*>(&Bs[kk][tx * 8 + 4]);
            #pragma unroll
            for (int i = 0; i < 8; i++)
                #pragma unroll
                for (int j = 0; j < 8; j++)
                    acc[i][j] = fmaf(ar[i], br[j], acc[i][j]);
        }
        __syncthreads();
    }

    // Fused LIF epilogue
    float bl[8];
    #pragma unroll
    for (int j = 0; j < 8; j++) bl[j] = bias[n0 + tx * 8 + j];

    #pragma unroll
    for (int i = 0; i < 8; i++) {
        int r = m0 + ty * 8 + i;
        size_t base = (size_t)r * N + n0 + tx * 8;
        #pragma unroll
        for (int v = 0; v < 2; v++) {
            float4 m4 = *reinterpret_cast<float4*>(&mem[base + v * 4]);
            float* mv = &m4.x;
            float sv[4];
            #pragma unroll
            for (int q = 0; q < 4; q++) {
                float h  = acc[i][v * 4 + q] + bl[v * 4 + q];
                float mo = mv[q];
                float mn = BETA * mo + h - ((mo > THR) ? THR : 0.f);
                mv[q] = mn;
                sv[q] = (mn > THR) ? 1.f : 0.f;
            }
            *reinterpret_cast<float4*>(&mem[base + v * 4]) = m4;
            *reinterpret_cast<float4*>(&sout[base + v * 4]) =
                make_float4(sv[0], sv[1], sv[2], sv[3]);
            if (LAYER == 2) {
                float4 p = *reinterpret_cast<float4*>(&g_spk[base + v * 4]);
                p.x += sv[0]; p.y += sv[1]; p.z += sv[2]; p.w += sv[3];
                *reinterpret_cast<float4*>(&g_spk[base + v * 4]) = p;
            }
        }
    }
}

// out[b,c] = (spk_sum[b,:]/NSTEPS) . Wo[c,:] + bo[c]
__global__ __launch_bounds__(256) void out_kernel(
    const float* __restrict__ Wo,
    const float* __restrict__ bo,
    float* __restrict__ out)
{
    __shared__ float wsh[64 * 129];
    const int tid = threadIdx.x;
    const int c  = tid & 63;
    const int rr = tid >> 6;              // 0..3
    const int b  = blockIdx.x * 4 + rr;

    float acc = 0.f;
    for (int k0 = 0; k0 < H2n; k0 += 128) {
        __syncthreads();
        #pragma unroll
        for (int it = 0; it < 8; it++) {
            int l  = tid + it * 256;      // 0..2047
            int c2 = l >> 5;              // 0..63
            int kk = (l & 31) * 4;        // 0..124
            float4 w4 = *reinterpret_cast<const float4*>(&Wo[(size_t)c2 * H2n + k0 + kk]);
            wsh[c2 * 129 + kk + 0] = w4.x;
            wsh[c2 * 129 + kk + 1] = w4.y;
            wsh[c2 * 129 + kk + 2] = w4.z;
            wsh[c2 * 129 + kk + 3] = w4.w;
        }
        __syncthreads();
        const float* sp = &g_spk[(size_t)b * H2n + k0];
        #pragma unroll
        for (int k = 0; k < 128; k += 4) {
            float4 s4 = *reinterpret_cast<const float4*>(sp + k);
            acc = fmaf(s4.x, wsh[c * 129 + k + 0], acc);
            acc = fmaf(s4.y, wsh[c * 129 + k + 1], acc);
            acc = fmaf(s4.z, wsh[c * 129 + k + 2], acc);
            acc = fmaf(s4.w, wsh[c * 129 + k + 3], acc);
        }
    }
    out[(size_t)b * Cn + c] = acc * (1.0f / NSTEPS) + bo[c];
}

extern "C" void kernel_launch(void* const* d_in, const int* in_sizes, int n_in,
                              void* d_out, int out_size)
{
    const float* x  = (const float*)d_in[0];
    const float* W1 = (const float*)d_in[1];
    const float* b1 = (const float*)d_in[2];
    const float* W2 = (const float*)d_in[3];
    const float* b2 = (const float*)d_in[4];
    const float* Wo = (const float*)d_in[5];
    const float* bo = (const float*)d_in[6];
    float* out = (float*)d_out;

    zero_kernel<<<512, 256>>>();

    dim3 blk(256);
    dim3 g1(H1n / 128, Bq / 128);
    dim3 g2(H2n / 128, Bq / 128);
    for (int t = 0; t < NSTEPS; t++) {
        gemm_step<1><<<g1, blk>>>(x, W1, b1, (t == 0) ? 1 : 0);
        gemm_step<2><<<g2, blk>>>(x, W2, b2, 0);
    }
    out_kernel<<<Bq / 4, 256>>>(Wo, bo, out);
}

// round 6
// speedup vs baseline: 2.2090x; 2.2075x over previous
#include <cuda_runtime.h>
#include <cuda_bf16.h>
#include <cstdint>

#define DINL __device__ __forceinline__

namespace {
constexpr int Bq = 4096, Dn = 1024, H1n = 2048, H2n = 1024, Cn = 64, NSTEPS = 20;
constexpr float BETA = 0.9f, THR = 1.0f;
constexpr int BM = 128, BN = 128, BK = 64, NSTAGE = 4;
constexpr int TILEB  = BM * 128;          // 16 KB per operand tile (128 rows x 128B)
constexpr int STAGEB = 2 * TILEB;         // 32 KB
constexpr int SMEM_DYN = NSTAGE * STAGEB + 1024;
}

__device__ float g_mem1[(size_t)Bq * H1n];
__device__ float g_mem2[(size_t)Bq * H2n];
__device__ float g_spk [(size_t)Bq * H2n];
__device__ __nv_bfloat16 g_s1[(size_t)Bq * H1n];
__device__ __nv_bfloat16 g_s2[(size_t)Bq * H2n];
__device__ __nv_bfloat16 g_x1[(size_t)Bq * Dn];
__device__ __nv_bfloat16 g_x2[(size_t)Bq * Dn];
__device__ __nv_bfloat16 g_x3[(size_t)Bq * Dn];
__device__ __nv_bfloat16 g_w1h[(size_t)H1n * Dn];
__device__ __nv_bfloat16 g_w1m[(size_t)H1n * Dn];
__device__ __nv_bfloat16 g_w1l[(size_t)H1n * Dn];
__device__ __nv_bfloat16 g_w2h[(size_t)H2n * H1n];
__device__ __nv_bfloat16 g_w2m[(size_t)H2n * H1n];
__device__ __nv_bfloat16 g_w2l[(size_t)H2n * H1n];

DINL uint32_t smem_u32(const void* p) {
    uint32_t a;
    asm("{ .reg .u64 t; cvta.to.shared.u64 t, %1; cvt.u32.u64 %0, t; }" : "=r"(a) : "l"(p));
    return a;
}
DINL void cp16(uint32_t dst, const void* src) {
    asm volatile("cp.async.cg.shared.global [%0], [%1], 16;" :: "r"(dst), "l"(src));
}
DINL void cp_commit() { asm volatile("cp.async.commit_group;" ::: "memory"); }
DINL void cp_wait2()  { asm volatile("cp.async.wait_group 2;" ::: "memory"); }
DINL void ldsm4(uint32_t& r0, uint32_t& r1, uint32_t& r2, uint32_t& r3, uint32_t addr) {
    asm volatile("ldmatrix.sync.aligned.m8n8.x4.shared.b16 {%0,%1,%2,%3}, [%4];"
                 : "=r"(r0), "=r"(r1), "=r"(r2), "=r"(r3) : "r"(addr));
}
DINL void mma16816(float* c, const uint32_t* a, const uint32_t* b) {
    asm volatile(
        "mma.sync.aligned.m16n8k16.row.col.f32.bf16.bf16.f32 "
        "{%0,%1,%2,%3},{%4,%5,%6,%7},{%8,%9},{%0,%1,%2,%3};"
        : "+f"(c[0]), "+f"(c[1]), "+f"(c[2]), "+f"(c[3])
        : "r"(a[0]), "r"(a[1]), "r"(a[2]), "r"(a[3]), "r"(b[0]), "r"(b[1]));
}

__global__ void zero_kernel() {
    size_t i = (size_t)blockIdx.x * blockDim.x + threadIdx.x;
    size_t stride = (size_t)gridDim.x * blockDim.x;
    const float4 z = make_float4(0.f, 0.f, 0.f, 0.f);
    for (size_t j = i; j < (size_t)Bq * H1n / 4; j += stride)
        reinterpret_cast<float4*>(g_mem1)[j] = z;
    for (size_t j = i; j < (size_t)Bq * H2n / 4; j += stride) {
        reinterpret_cast<float4*>(g_mem2)[j] = z;
        reinterpret_cast<float4*>(g_spk )[j] = z;
    }
}

// exact 3-way bf16 split: v == hi + mid + lo (fp32)
__global__ void split3_kernel(const float* __restrict__ src, size_t n, int which) {
    __nv_bfloat16 *h, *m, *l;
    if (which == 0)      { h = g_w1h; m = g_w1m; l = g_w1l; }
    else if (which == 1) { h = g_w2h; m = g_w2m; l = g_w2l; }
    else                 { h = g_x1;  m = g_x2;  l = g_x3;  }
    size_t i = (size_t)blockIdx.x * blockDim.x + threadIdx.x;
    size_t stride = (size_t)gridDim.x * blockDim.x;
    for (size_t j = i; j < n; j += stride) {
        float v = src[j];
        __nv_bfloat16 a = __float2bfloat16_rn(v);
        float r1 = v - __bfloat162float(a);
        __nv_bfloat16 b = __float2bfloat16_rn(r1);
        float r2 = r1 - __bfloat162float(b);
        h[j] = a; m[j] = b; l[j] = __float2bfloat16_rn(r2);
    }
}

// C[m,n] = sum_p A_p[m,:] . B_p[n,:]  via mma.sync bf16 + fused LIF epilogue.
template<int LAYER>
__global__ __launch_bounds__(256, 1) void gemm_mma(const float* __restrict__ bias, int t0) {
    constexpr int KDIM = (LAYER == 1) ? Dn  : H1n;
    constexpr int NDIM = (LAYER == 1) ? H1n : H2n;
    constexpr bool SPK = (LAYER == 2);
    constexpr int KC = KDIM / BK;

    extern __shared__ char smraw[];
    const uint32_t smbase = smem_u32(smraw);
    const uint32_t tb = (smbase + 1023u) & ~1023u;

    const int tid  = threadIdx.x;
    const int wid  = tid >> 5;
    const int lane = tid & 31;
    const int wm = wid >> 1;          // 0..3
    const int wn = wid & 1;           // 0..1
    const int m0   = blockIdx.y * BM;
    const int n0c  = blockIdx.x * BN;

    const __nv_bfloat16 *Asrc[9], *Bsrc[9];
    int npass;
    if (LAYER == 1) {
        const __nv_bfloat16* ws[3] = {g_w1h, g_w1m, g_w1l};
        if (t0) {
            npass = 9;
            const __nv_bfloat16* xs[3] = {g_x1, g_x2, g_x3};
            int idx = 0;
            for (int a = 0; a < 3; a++)
                for (int b = 0; b < 3; b++) { Asrc[idx] = xs[a]; Bsrc[idx] = ws[b]; idx++; }
        } else {
            npass = 3;
            for (int p = 0; p < 3; p++) { Asrc[p] = g_s2; Bsrc[p] = ws[p]; }
        }
    } else {
        npass = 3;
        const __nv_bfloat16* ws[3] = {g_w2h, g_w2m, g_w2l};
        for (int p = 0; p < 3; p++) { Asrc[p] = g_s1; Bsrc[p] = ws[p]; }
    }
    const int NC = npass * KC;

    float* mem = (LAYER == 1) ? g_mem1 : g_mem2;
    __nv_bfloat16* sout = (LAYER == 1) ? g_s1 : g_s2;

    // ---- loader: each thread moves 4x16B for A and for B per chunk ----
    const int lrow = tid >> 3;
    const int lc16 = tid & 7;
    auto load_chunk = [&](int j) {
        const int pp = j / KC;
        const int kc = j - pp * KC;
        const uint32_t sa = tb + (j & (NSTAGE - 1)) * STAGEB;
        const uint32_t sb = sa + TILEB;
        const __nv_bfloat16* As = Asrc[pp] + (size_t)m0  * KDIM + kc * BK + lc16 * 8;
        const __nv_bfloat16* Bs = Bsrc[pp] + (size_t)n0c * KDIM + kc * BK + lc16 * 8;
        #pragma unroll
        for (int q = 0; q < 4; q++) {
            int row = lrow + q * 32;
            uint32_t off = (uint32_t)row * 128 + (uint32_t)((lc16 ^ (row & 7)) << 4);
            cp16(sa + off, As + (size_t)row * KDIM);
            cp16(sb + off, Bs + (size_t)row * KDIM);
        }
        cp_commit();
    };

    // ---- per-lane ldmatrix address invariants ----
    const int aRow  = wm * 32 + (lane & 15);
    const uint32_t aXor = (uint32_t)(aRow & 7);
    uint32_t aob[2];
    #pragma unroll
    for (int f = 0; f < 2; f++) aob[f] = (uint32_t)(aRow + f * 16) * 128;
    const int bg     = lane >> 3;
    const int btile  = bg >> 1;
    const int bkhalf = bg & 1;
    const int bN     = wn * 64 + btile * 8 + (lane & 7);
    const uint32_t bXor = (uint32_t)(bN & 7);
    uint32_t bob[4];
    #pragma unroll
    for (int nf2 = 0; nf2 < 4; nf2++) bob[nf2] = (uint32_t)(bN + nf2 * 16) * 128;
    const uint32_t aC16 = (uint32_t)(lane >> 4);

    float acc[2][8][4];
    #pragma unroll
    for (int f = 0; f < 2; f++)
        #pragma unroll
        for (int nf = 0; nf < 8; nf++)
            #pragma unroll
            for (int q = 0; q < 4; q++) acc[f][nf][q] = 0.f;

    load_chunk(0);
    load_chunk(1);
    load_chunk(2);

    for (int i = 0; i < NC; i++) {
        cp_wait2();
        __syncthreads();
        const int j = i + 3;
        if (j < NC) load_chunk(j); else cp_commit();

        const uint32_t sa = tb + (i & (NSTAGE - 1)) * STAGEB;
        const uint32_t sb = sa + TILEB;
        #pragma unroll
        for (int ks = 0; ks < 4; ks++) {
            uint32_t af[2][4];
            #pragma unroll
            for (int f = 0; f < 2; f++) {
                uint32_t c16 = (uint32_t)(ks * 2) + aC16;
                ldsm4(af[f][0], af[f][1], af[f][2], af[f][3],
                      sa + aob[f] + ((c16 ^ aXor) << 4));
            }
            uint32_t bf[4][4];
            #pragma unroll
            for (int nf2 = 0; nf2 < 4; nf2++) {
                uint32_t c16 = (uint32_t)(ks * 2 + bkhalf);
                ldsm4(bf[nf2][0], bf[nf2][1], bf[nf2][2], bf[nf2][3],
                      sb + bob[nf2] + ((c16 ^ bXor) << 4));
            }
            #pragma unroll
            for (int f = 0; f < 2; f++)
                #pragma unroll
                for (int nf2 = 0; nf2 < 4; nf2++) {
                    mma16816(acc[f][nf2 * 2 + 0], af[f], &bf[nf2][0]);
                    mma16816(acc[f][nf2 * 2 + 1], af[f], &bf[nf2][2]);
                }
        }
    }

    // ---- fused LIF epilogue on accumulator fragments ----
    const int r4  = lane >> 2;
    const int cp2 = (lane & 3) * 2;
    const int ncolw = n0c + wn * 64;

    #pragma unroll
    for (int f = 0; f < 2; f++) {
        #pragma unroll
        for (int h = 0; h < 2; h++) {
            const int m = m0 + wm * 32 + f * 16 + h * 8 + r4;
            float* memrow = mem + (size_t)m * NDIM + ncolw;
            __nv_bfloat16* srow = sout + (size_t)m * NDIM + ncolw;
            float* spkrow = g_spk + (size_t)m * NDIM + ncolw;
            #pragma unroll
            for (int nf = 0; nf < 8; nf++) {
                const int nn = nf * 8 + cp2;
                float b0 = bias[ncolw + nn];
                float b1 = bias[ncolw + nn + 1];
                float h0 = acc[f][nf][2 * h + 0] + b0;
                float h1 = acc[f][nf][2 * h + 1] + b1;
                float2 mv = *reinterpret_cast<float2*>(memrow + nn);
                float n0v = BETA * mv.x + h0 - ((mv.x > THR) ? THR : 0.f);
                float n1v = BETA * mv.y + h1 - ((mv.y > THR) ? THR : 0.f);
                *reinterpret_cast<float2*>(memrow + nn) = make_float2(n0v, n1v);
                uint32_t s0 = (n0v > THR) ? 0x3F80u : 0u;
                uint32_t s1 = (n1v > THR) ? 0x3F80u : 0u;
                *reinterpret_cast<uint32_t*>(srow + nn) = s0 | (s1 << 16);
                if (SPK) {
                    float2 pk = *reinterpret_cast<float2*>(spkrow + nn);
                    pk.x += (n0v > THR) ? 1.f : 0.f;
                    pk.y += (n1v > THR) ? 1.f : 0.f;
                    *reinterpret_cast<float2*>(spkrow + nn) = pk;
                }
            }
        }
    }
}

__global__ __launch_bounds__(256) void out_kernel(
    const float* __restrict__ Wo,
    const float* __restrict__ bo,
    float* __restrict__ out)
{
    __shared__ float wsh[64 * 129];
    const int tid = threadIdx.x;
    const int c  = tid & 63;
    const int b  = blockIdx.x * 4 + (tid >> 6);

    float acc = 0.f;
    for (int k0 = 0; k0 < H2n; k0 += 128) {
        __syncthreads();
        #pragma unroll
        for (int it = 0; it < 8; it++) {
            int l  = tid + it * 256;
            int c2 = l >> 5;
            int kk = (l & 31) * 4;
            float4 w4 = *reinterpret_cast<const float4*>(&Wo[(size_t)c2 * H2n + k0 + kk]);
            wsh[c2 * 129 + kk + 0] = w4.x;
            wsh[c2 * 129 + kk + 1] = w4.y;
            wsh[c2 * 129 + kk + 2] = w4.z;
            wsh[c2 * 129 + kk + 3] = w4.w;
        }
        __syncthreads();
        const float* sp = &g_spk[(size_t)b * H2n + k0];
        #pragma unroll
        for (int k = 0; k < 128; k += 4) {
            float4 s4 = *reinterpret_cast<const float4*>(sp + k);
            acc = fmaf(s4.x, wsh[c * 129 + k + 0], acc);
            acc = fmaf(s4.y, wsh[c * 129 + k + 1], acc);
            acc = fmaf(s4.z, wsh[c * 129 + k + 2], acc);
            acc = fmaf(s4.w, wsh[c * 129 + k + 3], acc);
        }
    }
    out[(size_t)b * Cn + c] = acc * (1.0f / NSTEPS) + bo[c];
}

extern "C" void kernel_launch(void* const* d_in, const int* in_sizes, int n_in,
                              void* d_out, int out_size)
{
    const float* x  = (const float*)d_in[0];
    const float* W1 = (const float*)d_in[1];
    const float* b1 = (const float*)d_in[2];
    const float* W2 = (const float*)d_in[3];
    const float* b2 = (const float*)d_in[4];
    const float* Wo = (const float*)d_in[5];
    const float* bo = (const float*)d_in[6];
    float* out = (float*)d_out;

    cudaFuncSetAttribute(gemm_mma<1>, cudaFuncAttributeMaxDynamicSharedMemorySize, SMEM_DYN);
    cudaFuncSetAttribute(gemm_mma<2>, cudaFuncAttributeMaxDynamicSharedMemorySize, SMEM_DYN);

    zero_kernel<<<512, 256>>>();
    split3_kernel<<<512, 256>>>(W1, (size_t)H1n * Dn, 0);
    split3_kernel<<<512, 256>>>(W2, (size_t)H2n * H1n, 1);
    split3_kernel<<<512, 256>>>(x,  (size_t)Bq * Dn, 2);

    dim3 g1(H1n / BN, Bq / BM);
    dim3 g2(H2n / BN, Bq / BM);
    for (int t = 0; t < NSTEPS; t++) {
        gemm_mma<1><<<g1, 256, SMEM_DYN>>>(b1, (t == 0) ? 1 : 0);
        gemm_mma<2><<<g2, 256, SMEM_DYN>>>(b2, 0);
    }
    out_kernel<<<Bq / 4, 256>>>(Wo, bo, out);
}

// round 7
// speedup vs baseline: 2.4306x; 1.1003x over previous
#include <cuda_runtime.h>
#include <cuda_bf16.h>
#include <cstdint>

#define DINL __device__ __forceinline__

namespace {
constexpr int Bq = 4096, Dn = 1024, H1n = 2048, H2n = 1024, Cn = 64, NSTEPS = 20;
constexpr float BETA = 0.9f, THR = 1.0f;
constexpr int BM = 128, BN = 256, BK = 64;
constexpr int A_TILE = BM * 128;          // 16 KB
constexpr int B_TILE = BN * 128;          // 32 KB
constexpr int ASTAGE = 2, BSTAGE = 4;
constexpr int SMEM_DYN = ASTAGE * A_TILE + BSTAGE * B_TILE + 1024;  // ~161 KB
}

__device__ float g_mem1[(size_t)Bq * H1n];
__device__ float g_mem2[(size_t)Bq * H2n];
__device__ float g_spk [(size_t)Bq * H2n];
__device__ __nv_bfloat16 g_s1[(size_t)Bq * H1n];
__device__ __nv_bfloat16 g_s2[(size_t)Bq * H2n];
__device__ __nv_bfloat16 g_x1[(size_t)Bq * Dn];
__device__ __nv_bfloat16 g_x2[(size_t)Bq * Dn];
__device__ __nv_bfloat16 g_x3[(size_t)Bq * Dn];
__device__ __nv_bfloat16 g_w1h[(size_t)H1n * Dn];
__device__ __nv_bfloat16 g_w1m[(size_t)H1n * Dn];
__device__ __nv_bfloat16 g_w1l[(size_t)H1n * Dn];
__device__ __nv_bfloat16 g_w2h[(size_t)H2n * H1n];
__device__ __nv_bfloat16 g_w2m[(size_t)H2n * H1n];
__device__ __nv_bfloat16 g_w2l[(size_t)H2n * H1n];

DINL uint32_t smem_u32(const void* p) {
    uint32_t a;
    asm("{ .reg .u64 t; cvta.to.shared.u64 t, %1; cvt.u32.u64 %0, t; }" : "=r"(a) : "l"(p));
    return a;
}
DINL void cp16(uint32_t dst, const void* src) {
    asm volatile("cp.async.cg.shared.global [%0], [%1], 16;" :: "r"(dst), "l"(src));
}
DINL void cp_commit() { asm volatile("cp.async.commit_group;" ::: "memory"); }
DINL void cp_wait2()  { asm volatile("cp.async.wait_group 2;" ::: "memory"); }
DINL void ldsm4(uint32_t& r0, uint32_t& r1, uint32_t& r2, uint32_t& r3, uint32_t addr) {
    asm volatile("ldmatrix.sync.aligned.m8n8.x4.shared.b16 {%0,%1,%2,%3}, [%4];"
                 : "=r"(r0), "=r"(r1), "=r"(r2), "=r"(r3) : "r"(addr));
}
DINL void mma16816(float* c, const uint32_t* a, const uint32_t* b) {
    asm volatile(
        "mma.sync.aligned.m16n8k16.row.col.f32.bf16.bf16.f32 "
        "{%0,%1,%2,%3},{%4,%5,%6,%7},{%8,%9},{%0,%1,%2,%3};"
        : "+f"(c[0]), "+f"(c[1]), "+f"(c[2]), "+f"(c[3])
        : "r"(a[0]), "r"(a[1]), "r"(a[2]), "r"(a[3]), "r"(b[0]), "r"(b[1]));
}

__global__ void zero_kernel() {
    size_t i = (size_t)blockIdx.x * blockDim.x + threadIdx.x;
    size_t stride = (size_t)gridDim.x * blockDim.x;
    const float4 z = make_float4(0.f, 0.f, 0.f, 0.f);
    for (size_t j = i; j < (size_t)Bq * H1n / 4; j += stride)
        reinterpret_cast<float4*>(g_mem1)[j] = z;
    for (size_t j = i; j < (size_t)Bq * H2n / 4; j += stride) {
        reinterpret_cast<float4*>(g_mem2)[j] = z;
        reinterpret_cast<float4*>(g_spk )[j] = z;
    }
}

// exact 3-way bf16 split: v == hi + mid + lo (fp32)
__global__ void split3_kernel(const float* __restrict__ src, size_t n, int which) {
    __nv_bfloat16 *h, *m, *l;
    if (which == 0)      { h = g_w1h; m = g_w1m; l = g_w1l; }
    else if (which == 1) { h = g_w2h; m = g_w2m; l = g_w2l; }
    else                 { h = g_x1;  m = g_x2;  l = g_x3;  }
    size_t i = (size_t)blockIdx.x * blockDim.x + threadIdx.x;
    size_t stride = (size_t)gridDim.x * blockDim.x;
    for (size_t j = i; j < n; j += stride) {
        float v = src[j];
        __nv_bfloat16 a = __float2bfloat16_rn(v);
        float r1 = v - __bfloat162float(a);
        __nv_bfloat16 b = __float2bfloat16_rn(r1);
        float r2 = r1 - __bfloat162float(b);
        h[j] = a; m[j] = b; l[j] = __float2bfloat16_rn(r2);
    }
}

// C += sum over splits; chunk order kc-major so the A tile is loaded once per kc
// and reused by the 3 (or 9 at t0) split passes. Fused LIF epilogue.
template<int LAYER>
__global__ __launch_bounds__(256, 1) void gemm_mma(const float* __restrict__ bias, int t0) {
    constexpr int KDIM = (LAYER == 1) ? Dn  : H1n;
    constexpr int NDIM = (LAYER == 1) ? H1n : H2n;
    constexpr bool SPK = (LAYER == 2);
    constexpr int KC = KDIM / BK;

    extern __shared__ char smraw[];
    const uint32_t smbase = smem_u32(smraw);
    const uint32_t tbA = (smbase + 1023u) & ~1023u;
    const uint32_t tbB = tbA + ASTAGE * A_TILE;

    const int tid  = threadIdx.x;
    const int wid  = tid >> 5;
    const int lane = tid & 31;
    const int wm = wid >> 2;          // 0..1  (64 rows each)
    const int wn = wid & 3;           // 0..3  (64 cols each)
    const int m0  = blockIdx.y * BM;
    const int n0c = blockIdx.x * BN;

    // A sources (cycled by ai%agroup), B sources (cycled by j%3)
    const __nv_bfloat16* Alist[3];
    const __nv_bfloat16* Blist[3];
    int npass, agroup;   // agroup = npass/3 (1 or 3)
    if (LAYER == 1) {
        Blist[0] = g_w1h; Blist[1] = g_w1m; Blist[2] = g_w1l;
        if (t0) { npass = 9; agroup = 3; Alist[0] = g_x1; Alist[1] = g_x2; Alist[2] = g_x3; }
        else    { npass = 3; agroup = 1; Alist[0] = g_s2; Alist[1] = g_s2; Alist[2] = g_s2; }
    } else {
        npass = 3; agroup = 1;
        Blist[0] = g_w2h; Blist[1] = g_w2m; Blist[2] = g_w2l;
        Alist[0] = g_s1; Alist[1] = g_s1; Alist[2] = g_s1;
    }
    const int NC = npass * KC;

    float* mem = (LAYER == 1) ? g_mem1 : g_mem2;
    __nv_bfloat16* sout = (LAYER == 1) ? g_s1 : g_s2;

    // ---- loaders ----
    const int lrow = tid >> 3;          // 0..31
    const int lc16 = tid & 7;
    auto load_chunk = [&](int j) {
        // A: only when this chunk starts a new A tile (every 3 chunks)
        if (j % 3 == 0) {
            const int ai = j / 3;
            const int kcA = ai / agroup;
            const __nv_bfloat16* As = Alist[ai % agroup]
                + (size_t)m0 * KDIM + kcA * BK + lc16 * 8;
            const uint32_t sa = tbA + (ai & 1) * A_TILE;
            #pragma unroll
            for (int q = 0; q < 4; q++) {
                int row = lrow + q * 32;
                uint32_t off = (uint32_t)row * 128 + (uint32_t)((lc16 ^ (row & 7)) << 4);
                cp16(sa + off, As + (size_t)row * KDIM);
            }
        }
        const int kcB = j / npass;
        const __nv_bfloat16* Bs = Blist[j % 3]
            + (size_t)n0c * KDIM + kcB * BK + lc16 * 8;
        const uint32_t sb = tbB + (j & 3) * B_TILE;
        #pragma unroll
        for (int q = 0; q < 8; q++) {
            int row = lrow + q * 32;
            uint32_t off = (uint32_t)row * 128 + (uint32_t)((lc16 ^ (row & 7)) << 4);
            cp16(sb + off, Bs + (size_t)row * KDIM);
        }
        cp_commit();
    };

    // ---- per-lane ldmatrix invariants ----
    const int aRow  = wm * 64 + (lane & 15);
    const uint32_t aXor = (uint32_t)(aRow & 7);
    uint32_t aob[4];
    #pragma unroll
    for (int f = 0; f < 4; f++) aob[f] = (uint32_t)(aRow + f * 16) * 128;
    const uint32_t aC16 = (uint32_t)(lane >> 4);
    const int bg     = lane >> 3;
    const int btile  = bg >> 1;
    const int bkhalf = bg & 1;
    const int bN     = wn * 64 + btile * 8 + (lane & 7);
    const uint32_t bXor = (uint32_t)(bN & 7);
    uint32_t bob[4];
    #pragma unroll
    for (int nf2 = 0; nf2 < 4; nf2++) bob[nf2] = (uint32_t)(bN + nf2 * 16) * 128;

    float acc[4][8][4];
    #pragma unroll
    for (int f = 0; f < 4; f++)
        #pragma unroll
        for (int nf = 0; nf < 8; nf++)
            #pragma unroll
            for (int q = 0; q < 4; q++) acc[f][nf][q] = 0.f;

    load_chunk(0);
    load_chunk(1);
    load_chunk(2);

    for (int i = 0; i < NC; i++) {
        cp_wait2();
        __syncthreads();
        const int j = i + 3;
        if (j < NC) load_chunk(j); else cp_commit();

        const uint32_t sa = tbA + ((uint32_t)(i / 3) & 1) * A_TILE;
        const uint32_t sb = tbB + ((uint32_t)i & 3) * B_TILE;
        #pragma unroll
        for (int ks = 0; ks < 4; ks++) {
            uint32_t af[4][4];
            #pragma unroll
            for (int f = 0; f < 4; f++) {
                uint32_t c16 = (uint32_t)(ks * 2) + aC16;
                ldsm4(af[f][0], af[f][1], af[f][2], af[f][3],
                      sa + aob[f] + ((c16 ^ aXor) << 4));
            }
            uint32_t bf[4][4];
            #pragma unroll
            for (int nf2 = 0; nf2 < 4; nf2++) {
                uint32_t c16 = (uint32_t)(ks * 2 + bkhalf);
                ldsm4(bf[nf2][0], bf[nf2][1], bf[nf2][2], bf[nf2][3],
                      sb + bob[nf2] + ((c16 ^ bXor) << 4));
            }
            #pragma unroll
            for (int f = 0; f < 4; f++)
                #pragma unroll
                for (int nf2 = 0; nf2 < 4; nf2++) {
                    mma16816(acc[f][nf2 * 2 + 0], af[f], &bf[nf2][0]);
                    mma16816(acc[f][nf2 * 2 + 1], af[f], &bf[nf2][2]);
                }
        }
    }

    // ---- fused LIF epilogue ----
    const int r4  = lane >> 2;
    const int cp2 = (lane & 3) * 2;
    const int ncolw = n0c + wn * 64;

    #pragma unroll
    for (int f = 0; f < 4; f++) {
        #pragma unroll
        for (int h = 0; h < 2; h++) {
            const int m = m0 + wm * 64 + f * 16 + h * 8 + r4;
            float* memrow = mem + (size_t)m * NDIM + ncolw;
            __nv_bfloat16* srow = sout + (size_t)m * NDIM + ncolw;
            float* spkrow = g_spk + (size_t)m * NDIM + ncolw;
            #pragma unroll
            for (int nf = 0; nf < 8; nf++) {
                const int nn = nf * 8 + cp2;
                float b0 = bias[ncolw + nn];
                float b1 = bias[ncolw + nn + 1];
                float h0 = acc[f][nf][2 * h + 0] + b0;
                float h1 = acc[f][nf][2 * h + 1] + b1;
                float2 mv = *reinterpret_cast<float2*>(memrow + nn);
                float n0v = BETA * mv.x + h0 - ((mv.x > THR) ? THR : 0.f);
                float n1v = BETA * mv.y + h1 - ((mv.y > THR) ? THR : 0.f);
                *reinterpret_cast<float2*>(memrow + nn) = make_float2(n0v, n1v);
                uint32_t s0 = (n0v > THR) ? 0x3F80u : 0u;
                uint32_t s1 = (n1v > THR) ? 0x3F80u : 0u;
                *reinterpret_cast<uint32_t*>(srow + nn) = s0 | (s1 << 16);
                if (SPK) {
                    float2 pk = *reinterpret_cast<float2*>(spkrow + nn);
                    pk.x += (n0v > THR) ? 1.f : 0.f;
                    pk.y += (n1v > THR) ? 1.f : 0.f;
                    *reinterpret_cast<float2*>(spkrow + nn) = pk;
                }
            }
        }
    }
}

__global__ __launch_bounds__(256) void out_kernel(
    const float* __restrict__ Wo,
    const float* __restrict__ bo,
    float* __restrict__ out)
{
    __shared__ float wsh[64 * 129];
    const int tid = threadIdx.x;
    const int c  = tid & 63;
    const int b  = blockIdx.x * 4 + (tid >> 6);

    float acc = 0.f;
    for (int k0 = 0; k0 < H2n; k0 += 128) {
        __syncthreads();
        #pragma unroll
        for (int it = 0; it < 8; it++) {
            int l  = tid + it * 256;
            int c2 = l >> 5;
            int kk = (l & 31) * 4;
            float4 w4 = *reinterpret_cast<const float4*>(&Wo[(size_t)c2 * H2n + k0 + kk]);
            wsh[c2 * 129 + kk + 0] = w4.x;
            wsh[c2 * 129 + kk + 1] = w4.y;
            wsh[c2 * 129 + kk + 2] = w4.z;
            wsh[c2 * 129 + kk + 3] = w4.w;
        }
        __syncthreads();
        const float* sp = &g_spk[(size_t)b * H2n + k0];
        #pragma unroll
        for (int k = 0; k < 128; k += 4) {
            float4 s4 = *reinterpret_cast<const float4*>(sp + k);
            acc = fmaf(s4.x, wsh[c * 129 + k + 0], acc);
            acc = fmaf(s4.y, wsh[c * 129 + k + 1], acc);
            acc = fmaf(s4.z, wsh[c * 129 + k + 2], acc);
            acc = fmaf(s4.w, wsh[c * 129 + k + 3], acc);
        }
    }
    out[(size_t)b * Cn + c] = acc * (1.0f / NSTEPS) + bo[c];
}

extern "C" void kernel_launch(void* const* d_in, const int* in_sizes, int n_in,
                              void* d_out, int out_size)
{
    const float* x  = (const float*)d_in[0];
    const float* W1 = (const float*)d_in[1];
    const float* b1 = (const float*)d_in[2];
    const float* W2 = (const float*)d_in[3];
    const float* b2 = (const float*)d_in[4];
    const float* Wo = (const float*)d_in[5];
    const float* bo = (const float*)d_in[6];
    float* out = (float*)d_out;

    cudaFuncSetAttribute(gemm_mma<1>, cudaFuncAttributeMaxDynamicSharedMemorySize, SMEM_DYN);
    cudaFuncSetAttribute(gemm_mma<2>, cudaFuncAttributeMaxDynamicSharedMemorySize, SMEM_DYN);

    zero_kernel<<<512, 256>>>();
    split3_kernel<<<512, 256>>>(W1, (size_t)H1n * Dn, 0);
    split3_kernel<<<512, 256>>>(W2, (size_t)H2n * H1n, 1);
    split3_kernel<<<512, 256>>>(x,  (size_t)Bq * Dn, 2);

    dim3 g1(H1n / BN, Bq / BM);
    dim3 g2(H2n / BN, Bq / BM);
    for (int t = 0; t < NSTEPS; t++) {
        gemm_mma<1><<<g1, 256, SMEM_DYN>>>(b1, (t == 0) ? 1 : 0);
        gemm_mma<2><<<g2, 256, SMEM_DYN>>>(b2, 0);
    }
    out_kernel<<<Bq / 4, 256>>>(Wo, bo, out);
}

// round 8
// speedup vs baseline: 2.9733x; 1.2233x over previous
#include <cuda_runtime.h>
#include <cuda_bf16.h>
#include <cstdint>

#define DINL __device__ __forceinline__

namespace {
constexpr int Bq = 4096, Dn = 1024, H1n = 2048, H2n = 1024, Cn = 64, NSTEPS = 20;
constexpr float BETA = 0.9f, THR = 1.0f;
// bf16 t0 kernel tiles
constexpr int T0_BM = 128, T0_BN = 256;
constexpr int T0_A_TILE = T0_BM * 128, T0_B_TILE = T0_BN * 128;
constexpr int SMEM_T0 = 2 * T0_A_TILE + 4 * T0_B_TILE + 1024;
// int8 kernel tiles: CTA 128x128, BK=128 int8 (128B rows)
constexpr int I8_TILE = 128 * 128;           // 16 KB
constexpr int I8_STAGE = 2 * I8_TILE;        // 32 KB
constexpr int SMEM_I8 = 4 * I8_STAGE + 1024;
}

__device__ float g_mem1[(size_t)Bq * H1n];
__device__ float g_mem2[(size_t)Bq * H2n];
__device__ float g_spk [(size_t)Bq * H2n];
__device__ int8_t g_s1b[(size_t)Bq * H1n];
__device__ int8_t g_s2b[(size_t)Bq * H2n];
// bf16 splits (t0 only)
__device__ __nv_bfloat16 g_x1[(size_t)Bq * Dn];
__device__ __nv_bfloat16 g_x2[(size_t)Bq * Dn];
__device__ __nv_bfloat16 g_x3[(size_t)Bq * Dn];
__device__ __nv_bfloat16 g_w1h[(size_t)H1n * Dn];
__device__ __nv_bfloat16 g_w1m[(size_t)H1n * Dn];
__device__ __nv_bfloat16 g_w1l[(size_t)H1n * Dn];
// int8 4-window weight splits
__device__ int8_t g_w1i0[(size_t)H1n * Dn];
__device__ int8_t g_w1i1[(size_t)H1n * Dn];
__device__ int8_t g_w1i2[(size_t)H1n * Dn];
__device__ int8_t g_w1i3[(size_t)H1n * Dn];
__device__ int8_t g_w2i0[(size_t)H2n * H1n];
__device__ int8_t g_w2i1[(size_t)H2n * H1n];
__device__ int8_t g_w2i2[(size_t)H2n * H1n];
__device__ int8_t g_w2i3[(size_t)H2n * H1n];

DINL uint32_t smem_u32(const void* p) {
    uint32_t a;
    asm("{ .reg .u64 t; cvta.to.shared.u64 t, %1; cvt.u32.u64 %0, t; }" : "=r"(a) : "l"(p));
    return a;
}
DINL void cp16(uint32_t dst, const void* src) {
    asm volatile("cp.async.cg.shared.global [%0], [%1], 16;" :: "r"(dst), "l"(src));
}
DINL void cp_commit() { asm volatile("cp.async.commit_group;" ::: "memory"); }
DINL void cp_wait2()  { asm volatile("cp.async.wait_group 2;" ::: "memory"); }
DINL void ldsm4(uint32_t& r0, uint32_t& r1, uint32_t& r2, uint32_t& r3, uint32_t addr) {
    asm volatile("ldmatrix.sync.aligned.m8n8.x4.shared.b16 {%0,%1,%2,%3}, [%4];"
                 : "=r"(r0), "=r"(r1), "=r"(r2), "=r"(r3) : "r"(addr));
}
DINL void mma16816(float* c, const uint32_t* a, const uint32_t* b) {
    asm volatile(
        "mma.sync.aligned.m16n8k16.row.col.f32.bf16.bf16.f32 "
        "{%0,%1,%2,%3},{%4,%5,%6,%7},{%8,%9},{%0,%1,%2,%3};"
        : "+f"(c[0]), "+f"(c[1]), "+f"(c[2]), "+f"(c[3])
        : "r"(a[0]), "r"(a[1]), "r"(a[2]), "r"(a[3]), "r"(b[0]), "r"(b[1]));
}
DINL void mma16832s8(int* c, const uint32_t* a, const uint32_t* b) {
    asm volatile(
        "mma.sync.aligned.m16n8k32.row.col.s32.s8.s8.s32 "
        "{%0,%1,%2,%3},{%4,%5,%6,%7},{%8,%9},{%0,%1,%2,%3};"
        : "+r"(c[0]), "+r"(c[1]), "+r"(c[2]), "+r"(c[3])
        : "r"(a[0]), "r"(a[1]), "r"(a[2]), "r"(a[3]), "r"(b[0]), "r"(b[1]));
}

__global__ void zero_kernel() {
    size_t i = (size_t)blockIdx.x * blockDim.x + threadIdx.x;
    size_t stride = (size_t)gridDim.x * blockDim.x;
    const float4 z = make_float4(0.f, 0.f, 0.f, 0.f);
    for (size_t j = i; j < (size_t)Bq * H1n / 4; j += stride)
        reinterpret_cast<float4*>(g_mem1)[j] = z;
    for (size_t j = i; j < (size_t)Bq * H2n / 4; j += stride) {
        reinterpret_cast<float4*>(g_mem2)[j] = z;
        reinterpret_cast<float4*>(g_spk )[j] = z;
    }
}

// exact 3-way bf16 split (for t0 operands)
__global__ void split3_kernel(const float* __restrict__ src, size_t n, int which) {
    __nv_bfloat16 *h, *m, *l;
    if (which == 0) { h = g_w1h; m = g_w1m; l = g_w1l; }
    else            { h = g_x1;  m = g_x2;  l = g_x3;  }
    size_t i = (size_t)blockIdx.x * blockDim.x + threadIdx.x;
    size_t stride = (size_t)gridDim.x * blockDim.x;
    for (size_t j = i; j < n; j += stride) {
        float v = src[j];
        __nv_bfloat16 a = __float2bfloat16_rn(v);
        float r1 = v - __bfloat162float(a);
        __nv_bfloat16 b = __float2bfloat16_rn(r1);
        float r2 = r1 - __bfloat162float(b);
        h[j] = a; m[j] = b; l[j] = __float2bfloat16_rn(r2);
    }
}

// 4-window int8 split: w = i0*2^-9 + i1*2^-16 + i2*2^-23 + i3*2^-30 (+ residual <= 2^-31)
__global__ void split4_kernel(const float* __restrict__ src, size_t n, int which) {
    int8_t *p0, *p1, *p2, *p3;
    if (which == 0) { p0 = g_w1i0; p1 = g_w1i1; p2 = g_w1i2; p3 = g_w1i3; }
    else            { p0 = g_w2i0; p1 = g_w2i1; p2 = g_w2i2; p3 = g_w2i3; }
    size_t i = (size_t)blockIdx.x * blockDim.x + threadIdx.x;
    size_t stride = (size_t)gridDim.x * blockDim.x;
    for (size_t j = i; j < n; j += stride) {
        float v = src[j];
        float t0 = fminf(fmaxf(rintf(v * 0x1p9f), -127.f), 127.f);
        float r  = v - t0 * 0x1p-9f;
        float t1 = fminf(fmaxf(rintf(r * 0x1p16f), -127.f), 127.f);
        r -= t1 * 0x1p-16f;
        float t2 = fminf(fmaxf(rintf(r * 0x1p23f), -127.f), 127.f);
        r -= t2 * 0x1p-23f;
        float t3 = fminf(fmaxf(rintf(r * 0x1p30f), -127.f), 127.f);
        p0[j] = (int8_t)(int)t0;
        p1[j] = (int8_t)(int)t1;
        p2[j] = (int8_t)(int)t2;
        p3[j] = (int8_t)(int)t3;
    }
}

// ---------------- t0 layer-1 GEMM: bf16 3x3 exact (x dense) ----------------
__global__ __launch_bounds__(256, 1) void gemm_t0(const float* __restrict__ bias) {
    constexpr int KDIM = Dn, NDIM = H1n;
    constexpr int KC = KDIM / 64;          // 16
    constexpr int NC = 9 * KC;             // 144

    extern __shared__ char smraw[];
    const uint32_t smbase = smem_u32(smraw);
    const uint32_t tbA = (smbase + 1023u) & ~1023u;
    const uint32_t tbB = tbA + 2 * T0_A_TILE;

    const int tid  = threadIdx.x;
    const int wid  = tid >> 5;
    const int lane = tid & 31;
    const int wm = wid >> 2;
    const int wn = wid & 3;
    const int m0  = blockIdx.y * T0_BM;
    const int n0c = blockIdx.x * T0_BN;

    const __nv_bfloat16* xs[3] = {g_x1, g_x2, g_x3};
    const __nv_bfloat16* ws[3] = {g_w1h, g_w1m, g_w1l};

    const int lrow = tid >> 3;
    const int lc16 = tid & 7;
    auto load_chunk = [&](int j) {
        if (j % 3 == 0) {
            const int ai = j / 3;                  // 0..47
            const int kcA = ai / 3;
            const __nv_bfloat16* As = xs[ai % 3] + (size_t)m0 * KDIM + kcA * 64 + lc16 * 8;
            const uint32_t sa = tbA + (ai & 1) * T0_A_TILE;
            #pragma unroll
            for (int q = 0; q < 4; q++) {
                int row = lrow + q * 32;
                uint32_t off = (uint32_t)row * 128 + (uint32_t)((lc16 ^ (row & 7)) << 4);
                cp16(sa + off, As + (size_t)row * KDIM);
            }
        }
        const int kcB = j / 9;
        const __nv_bfloat16* Bs = ws[j % 3] + (size_t)n0c * KDIM + kcB * 64 + lc16 * 8;
        const uint32_t sb = tbB + (j & 3) * T0_B_TILE;
        #pragma unroll
        for (int q = 0; q < 8; q++) {
            int row = lrow + q * 32;
            uint32_t off = (uint32_t)row * 128 + (uint32_t)((lc16 ^ (row & 7)) << 4);
            cp16(sb + off, Bs + (size_t)row * KDIM);
        }
        cp_commit();
    };

    const int aRow  = wm * 64 + (lane & 15);
    const uint32_t aXor = (uint32_t)(aRow & 7);
    uint32_t aob[4];
    #pragma unroll
    for (int f = 0; f < 4; f++) aob[f] = (uint32_t)(aRow + f * 16) * 128;
    const uint32_t aC16 = (uint32_t)(lane >> 4);
    const int bg     = lane >> 3;
    const int btile  = bg >> 1;
    const int bkhalf = bg & 1;
    const int bN     = wn * 64 + btile * 8 + (lane & 7);
    const uint32_t bXor = (uint32_t)(bN & 7);
    uint32_t bob[4];
    #pragma unroll
    for (int nf2 = 0; nf2 < 4; nf2++) bob[nf2] = (uint32_t)(bN + nf2 * 16) * 128;

    float acc[4][8][4];
    #pragma unroll
    for (int f = 0; f < 4; f++)
        #pragma unroll
        for (int nf = 0; nf < 8; nf++)
            #pragma unroll
            for (int q = 0; q < 4; q++) acc[f][nf][q] = 0.f;

    load_chunk(0); load_chunk(1); load_chunk(2);

    for (int i = 0; i < NC; i++) {
        cp_wait2();
        __syncthreads();
        const int j = i + 3;
        if (j < NC) load_chunk(j); else cp_commit();

        const uint32_t sa = tbA + ((uint32_t)(i / 3) & 1) * T0_A_TILE;
        const uint32_t sb = tbB + ((uint32_t)i & 3) * T0_B_TILE;
        #pragma unroll
        for (int ks = 0; ks < 4; ks++) {
            uint32_t af[4][4];
            #pragma unroll
            for (int f = 0; f < 4; f++) {
                uint32_t c16 = (uint32_t)(ks * 2) + aC16;
                ldsm4(af[f][0], af[f][1], af[f][2], af[f][3],
                      sa + aob[f] + ((c16 ^ aXor) << 4));
            }
            uint32_t bf[4][4];
            #pragma unroll
            for (int nf2 = 0; nf2 < 4; nf2++) {
                uint32_t c16 = (uint32_t)(ks * 2 + bkhalf);
                ldsm4(bf[nf2][0], bf[nf2][1], bf[nf2][2], bf[nf2][3],
                      sb + bob[nf2] + ((c16 ^ bXor) << 4));
            }
            #pragma unroll
            for (int f = 0; f < 4; f++)
                #pragma unroll
                for (int nf2 = 0; nf2 < 4; nf2++) {
                    mma16816(acc[f][nf2 * 2 + 0], af[f], &bf[nf2][0]);
                    mma16816(acc[f][nf2 * 2 + 1], af[f], &bf[nf2][2]);
                }
        }
    }

    const int r4  = lane >> 2;
    const int cp2 = (lane & 3) * 2;
    const int ncolw = n0c + wn * 64;
    #pragma unroll
    for (int f = 0; f < 4; f++) {
        #pragma unroll
        for (int h = 0; h < 2; h++) {
            const int m = m0 + wm * 64 + f * 16 + h * 8 + r4;
            float* memrow = g_mem1 + (size_t)m * NDIM + ncolw;
            int8_t* srow = g_s1b + (size_t)m * NDIM + ncolw;
            #pragma unroll
            for (int nf = 0; nf < 8; nf++) {
                const int nn = nf * 8 + cp2;
                float h0 = acc[f][nf][2 * h + 0] + bias[ncolw + nn];
                float h1 = acc[f][nf][2 * h + 1] + bias[ncolw + nn + 1];
                float2 mv = *reinterpret_cast<float2*>(memrow + nn);
                float n0v = BETA * mv.x + h0 - ((mv.x > THR) ? THR : 0.f);
                float n1v = BETA * mv.y + h1 - ((mv.y > THR) ? THR : 0.f);
                *reinterpret_cast<float2*>(memrow + nn) = make_float2(n0v, n1v);
                char2 sp;
                sp.x = (n0v > THR) ? 1 : 0;
                sp.y = (n1v > THR) ? 1 : 0;
                *reinterpret_cast<char2*>(srow + nn) = sp;
            }
        }
    }
}

// ---------------- int8 spike GEMM: 4-pass shift-chained + fused LIF ----------------
template<int LAYER>
__global__ __launch_bounds__(256, 1) void gemm_i8(const float* __restrict__ bias) {
    constexpr int KDIM = (LAYER == 1) ? H2n : H1n;
    constexpr int NDIM = (LAYER == 1) ? H1n : H2n;
    constexpr bool SPK = (LAYER == 2);
    constexpr int KC = KDIM / 128;
    constexpr int NC = 4 * KC;

    extern __shared__ char smraw[];
    const uint32_t smbase = smem_u32(smraw);
    const uint32_t tb = (smbase + 1023u) & ~1023u;

    const int tid  = threadIdx.x;
    const int wid  = tid >> 5;
    const int lane = tid & 31;
    const int wm = wid >> 2;          // 0..1 (64 rows)
    const int wn = wid & 3;           // 0..3 (32 cols)
    const int m0  = blockIdx.y * 128;
    const int n0c = blockIdx.x * 128;

    const int8_t* A = (LAYER == 1) ? g_s2b : g_s1b;
    const int8_t* W[4];
    if (LAYER == 1) { W[0] = g_w1i0; W[1] = g_w1i1; W[2] = g_w1i2; W[3] = g_w1i3; }
    else            { W[0] = g_w2i0; W[1] = g_w2i1; W[2] = g_w2i2; W[3] = g_w2i3; }

    float* mem = (LAYER == 1) ? g_mem1 : g_mem2;
    int8_t* sout = (LAYER == 1) ? g_s1b : g_s2b;

    const int lrow = tid >> 3;
    const int lc16 = tid & 7;
    auto load_chunk = [&](int j) {
        const int p  = j / KC;
        const int kc = j - p * KC;
        const uint32_t sa = tb + (j & 3) * I8_STAGE;
        const uint32_t sb = sa + I8_TILE;
        const int8_t* As = A + (size_t)m0 * KDIM + kc * 128 + lc16 * 16;
        const int8_t* Bs = W[p] + (size_t)n0c * KDIM + kc * 128 + lc16 * 16;
        #pragma unroll
        for (int q = 0; q < 4; q++) {
            int row = lrow + q * 32;
            uint32_t off = (uint32_t)row * 128 + (uint32_t)((lc16 ^ (row & 7)) << 4);
            cp16(sa + off, As + (size_t)row * KDIM);
            cp16(sb + off, Bs + (size_t)row * KDIM);
        }
        cp_commit();
    };

    const int aRow  = wm * 64 + (lane & 15);
    const uint32_t aXor = (uint32_t)(aRow & 7);
    uint32_t aob[4];
    #pragma unroll
    for (int f = 0; f < 4; f++) aob[f] = (uint32_t)(aRow + f * 16) * 128;
    const uint32_t aC16 = (uint32_t)(lane >> 4);
    const int bg     = lane >> 3;
    const int btile  = bg >> 1;
    const int bkhalf = bg & 1;
    const int bN     = wn * 32 + btile * 8 + (lane & 7);
    const uint32_t bXor = (uint32_t)(bN & 7);
    uint32_t bob[2];
    #pragma unroll
    for (int n2 = 0; n2 < 2; n2++) bob[n2] = (uint32_t)(bN + n2 * 16) * 128;

    int accA[4][4][4], accB[4][4][4];
    #pragma unroll
    for (int f = 0; f < 4; f++)
        #pragma unroll
        for (int o = 0; o < 4; o++)
            #pragma unroll
            for (int q = 0; q < 4; q++) { accA[f][o][q] = 0; accB[f][o][q] = 0; }

    load_chunk(0); load_chunk(1); load_chunk(2);

    for (int i = 0; i < NC; i++) {
        cp_wait2();
        __syncthreads();
        const int j = i + 3;
        if (j < NC) load_chunk(j); else cp_commit();

        const uint32_t sa = tb + ((uint32_t)i & 3) * I8_STAGE;
        const uint32_t sb = sa + I8_TILE;
        const int p = i / KC;

        auto run = [&](int (&acc)[4][4][4]) {
            #pragma unroll
            for (int ks = 0; ks < 4; ks++) {
                uint32_t af[4][4];
                #pragma unroll
                for (int f = 0; f < 4; f++) {
                    uint32_t c16 = (uint32_t)(ks * 2) + aC16;
                    ldsm4(af[f][0], af[f][1], af[f][2], af[f][3],
                          sa + aob[f] + ((c16 ^ aXor) << 4));
                }
                uint32_t bf[2][4];
                #pragma unroll
                for (int n2 = 0; n2 < 2; n2++) {
                    uint32_t c16 = (uint32_t)(ks * 2 + bkhalf);
                    ldsm4(bf[n2][0], bf[n2][1], bf[n2][2], bf[n2][3],
                          sb + bob[n2] + ((c16 ^ bXor) << 4));
                }
                #pragma unroll
                for (int f = 0; f < 4; f++)
                    #pragma unroll
                    for (int o = 0; o < 4; o++)
                        mma16832s8(acc[f][o], af[f], &bf[o >> 1][(o & 1) * 2]);
            }
        };
        if (p < 2) run(accA); else run(accB);

        if (i == KC - 1) {
            #pragma unroll
            for (int f = 0; f < 4; f++)
                #pragma unroll
                for (int o = 0; o < 4; o++)
                    #pragma unroll
                    for (int q = 0; q < 4; q++) accA[f][o][q] *= 128;
        }
        if (i == 3 * KC - 1) {
            #pragma unroll
            for (int f = 0; f < 4; f++)
                #pragma unroll
                for (int o = 0; o < 4; o++)
                    #pragma unroll
                    for (int q = 0; q < 4; q++) accB[f][o][q] *= 128;
        }
    }

    // epilogue: exact recombination + LIF
    const int r4  = lane >> 2;
    const int cp2 = (lane & 3) * 2;
    const int ncolw = n0c + wn * 32;
    #pragma unroll
    for (int f = 0; f < 4; f++) {
        #pragma unroll
        for (int h = 0; h < 2; h++) {
            const int m = m0 + wm * 64 + f * 16 + h * 8 + r4;
            float* memrow = mem + (size_t)m * NDIM + ncolw;
            int8_t* srow = sout + (size_t)m * NDIM + ncolw;
            float* spkrow = g_spk + (size_t)m * NDIM + ncolw;
            #pragma unroll
            for (int o = 0; o < 4; o++) {
                const int nn = o * 8 + cp2;
                float hv[2];
                #pragma unroll
                for (int q = 0; q < 2; q++) {
                    int va = accA[f][o][2 * h + q];
                    int vb = accB[f][o][2 * h + q];
                    int ah = va >> 7, al = va - (ah << 7);
                    int bh = vb >> 7, bl = vb - (bh << 7);
                    hv[q] = bias[ncolw + nn + q]
                          + (float)ah * 0x1p-9f  + (float)al * 0x1p-16f
                          + (float)bh * 0x1p-23f + (float)bl * 0x1p-30f;
                }
                float2 mv = *reinterpret_cast<float2*>(memrow + nn);
                float n0v = BETA * mv.x + hv[0] - ((mv.x > THR) ? THR : 0.f);
                float n1v = BETA * mv.y + hv[1] - ((mv.y > THR) ? THR : 0.f);
                *reinterpret_cast<float2*>(memrow + nn) = make_float2(n0v, n1v);
                char2 sp;
                sp.x = (n0v > THR) ? 1 : 0;
                sp.y = (n1v > THR) ? 1 : 0;
                *reinterpret_cast<char2*>(srow + nn) = sp;
                if (SPK) {
                    float2 pk = *reinterpret_cast<float2*>(spkrow + nn);
                    pk.x += (n0v > THR) ? 1.f : 0.f;
                    pk.y += (n1v > THR) ? 1.f : 0.f;
                    *reinterpret_cast<float2*>(spkrow + nn) = pk;
                }
            }
        }
    }
}

__global__ __launch_bounds__(256) void out_kernel(
    const float* __restrict__ Wo,
    const float* __restrict__ bo,
    float* __restrict__ out)
{
    __shared__ float wsh[64 * 129];
    const int tid = threadIdx.x;
    const int c  = tid & 63;
    const int b  = blockIdx.x * 4 + (tid >> 6);

    float acc = 0.f;
    for (int k0 = 0; k0 < H2n; k0 += 128) {
        __syncthreads();
        #pragma unroll
        for (int it = 0; it < 8; it++) {
            int l  = tid + it * 256;
            int c2 = l >> 5;
            int kk = (l & 31) * 4;
            float4 w4 = *reinterpret_cast<const float4*>(&Wo[(size_t)c2 * H2n + k0 + kk]);
            wsh[c2 * 129 + kk + 0] = w4.x;
            wsh[c2 * 129 + kk + 1] = w4.y;
            wsh[c2 * 129 + kk + 2] = w4.z;
            wsh[c2 * 129 + kk + 3] = w4.w;
        }
        __syncthreads();
        const float* sp = &g_spk[(size_t)b * H2n + k0];
        #pragma unroll
        for (int k = 0; k < 128; k += 4) {
            float4 s4 = *reinterpret_cast<const float4*>(sp + k);
            acc = fmaf(s4.x, wsh[c * 129 + k + 0], acc);
            acc = fmaf(s4.y, wsh[c * 129 + k + 1], acc);
            acc = fmaf(s4.z, wsh[c * 129 + k + 2], acc);
            acc = fmaf(s4.w, wsh[c * 129 + k + 3], acc);
        }
    }
    out[(size_t)b * Cn + c] = acc * (1.0f / NSTEPS) + bo[c];
}

extern "C" void kernel_launch(void* const* d_in, const int* in_sizes, int n_in,
                              void* d_out, int out_size)
{
    const float* x  = (const float*)d_in[0];
    const float* W1 = (const float*)d_in[1];
    const float* b1 = (const float*)d_in[2];
    const float* W2 = (const float*)d_in[3];
    const float* b2 = (const float*)d_in[4];
    const float* Wo = (const float*)d_in[5];
    const float* bo = (const float*)d_in[6];
    float* out = (float*)d_out;

    cudaFuncSetAttribute(gemm_t0, cudaFuncAttributeMaxDynamicSharedMemorySize, SMEM_T0);
    cudaFuncSetAttribute(gemm_i8<1>, cudaFuncAttributeMaxDynamicSharedMemorySize, SMEM_I8);
    cudaFuncSetAttribute(gemm_i8<2>, cudaFuncAttributeMaxDynamicSharedMemorySize, SMEM_I8);

    zero_kernel<<<512, 256>>>();
    split3_kernel<<<512, 256>>>(W1, (size_t)H1n * Dn, 0);
    split3_kernel<<<512, 256>>>(x,  (size_t)Bq * Dn, 1);
    split4_kernel<<<512, 256>>>(W1, (size_t)H1n * Dn, 0);
    split4_kernel<<<512, 256>>>(W2, (size_t)H2n * H1n, 1);

    dim3 gt0(H1n / T0_BN, Bq / T0_BM);          // (8, 32)
    dim3 g1(H1n / 128, Bq / 128);               // (16, 32)
    dim3 g2(H2n / 128, Bq / 128);               // (8, 32)

    gemm_t0<<<gt0, 256, SMEM_T0>>>(b1);
    gemm_i8<2><<<g2, 256, SMEM_I8>>>(b2);
    for (int t = 1; t < NSTEPS; t++) {
        gemm_i8<1><<<g1, 256, SMEM_I8>>>(b1);
        gemm_i8<2><<<g2, 256, SMEM_I8>>>(b2);
    }
    out_kernel<<<Bq / 4, 256>>>(Wo, bo, out);
}

// round 11
// speedup vs baseline: 3.8019x; 1.2787x over previous
#include <cuda_runtime.h>
#include <cuda_bf16.h>
#include <cstdint>

#define DINL __device__ __forceinline__

namespace {
constexpr int Bq = 4096, Dn = 1024, H1n = 2048, H2n = 1024, Cn = 64, NSTEPS = 20;
constexpr float BETA = 0.9f, THR = 1.0f;
// t0 bf16 kernel: CTA 128x256, combined stage A(16K)+B(32K)
constexpr int T0_A = 128 * 128, T0_B = 256 * 128;
constexpr int T0_STAGE = T0_A + T0_B;               // 48 KB
constexpr int SMEM_T0 = 4 * T0_STAGE + 1024;        // ~193 KB
// int8 kernel: CTA 64x128, stage A(8K)+B(16K)
constexpr int I8_A = 64 * 128, I8_B = 128 * 128;
constexpr int I8_STAGE = I8_A + I8_B;               // 24 KB
constexpr int SMEM_I8 = 4 * I8_STAGE + 1024;        // ~97 KB -> 2 CTAs/SM
}

__device__ float g_mem1[(size_t)Bq * H1n];
__device__ float g_mem2[(size_t)Bq * H2n];
__device__ float g_spk [(size_t)Bq * H2n];
__device__ int8_t g_s1b[(size_t)Bq * H1n];
__device__ int8_t g_s2b[(size_t)Bq * H2n];
// bf16 splits (t0 only)
__device__ __nv_bfloat16 g_x1[(size_t)Bq * Dn];
__device__ __nv_bfloat16 g_x2[(size_t)Bq * Dn];
__device__ __nv_bfloat16 g_x3[(size_t)Bq * Dn];
__device__ __nv_bfloat16 g_w1h[(size_t)H1n * Dn];
__device__ __nv_bfloat16 g_w1m[(size_t)H1n * Dn];
__device__ __nv_bfloat16 g_w1l[(size_t)H1n * Dn];
// int8 4-window weight splits
__device__ int8_t g_w1i0[(size_t)H1n * Dn];
__device__ int8_t g_w1i1[(size_t)H1n * Dn];
__device__ int8_t g_w1i2[(size_t)H1n * Dn];
__device__ int8_t g_w1i3[(size_t)H1n * Dn];
__device__ int8_t g_w2i0[(size_t)H2n * H1n];
__device__ int8_t g_w2i1[(size_t)H2n * H1n];
__device__ int8_t g_w2i2[(size_t)H2n * H1n];
__device__ int8_t g_w2i3[(size_t)H2n * H1n];

DINL uint32_t smem_u32(const void* p) {
    uint32_t a;
    asm("{ .reg .u64 t; cvta.to.shared.u64 t, %1; cvt.u32.u64 %0, t; }" : "=r"(a) : "l"(p));
    return a;
}
DINL void cp16(uint32_t dst, const void* src) {
    asm volatile("cp.async.cg.shared.global [%0], [%1], 16;" :: "r"(dst), "l"(src));
}
DINL void cp_commit() { asm volatile("cp.async.commit_group;" ::: "memory"); }
DINL void cp_wait2()  { asm volatile("cp.async.wait_group 2;" ::: "memory"); }
DINL void ldsm4(uint32_t& r0, uint32_t& r1, uint32_t& r2, uint32_t& r3, uint32_t addr) {
    asm volatile("ldmatrix.sync.aligned.m8n8.x4.shared.b16 {%0,%1,%2,%3}, [%4];"
                 : "=r"(r0), "=r"(r1), "=r"(r2), "=r"(r3) : "r"(addr));
}
DINL void mma16816(float* c, const uint32_t* a, const uint32_t* b) {
    asm volatile(
        "mma.sync.aligned.m16n8k16.row.col.f32.bf16.bf16.f32 "
        "{%0,%1,%2,%3},{%4,%5,%6,%7},{%8,%9},{%0,%1,%2,%3};"
        : "+f"(c[0]), "+f"(c[1]), "+f"(c[2]), "+f"(c[3])
        : "r"(a[0]), "r"(a[1]), "r"(a[2]), "r"(a[3]), "r"(b[0]), "r"(b[1]));
}
DINL void mma16832s8(int* c, const uint32_t* a, const uint32_t* b) {
    asm volatile(
        "mma.sync.aligned.m16n8k32.row.col.s32.s8.s8.s32 "
        "{%0,%1,%2,%3},{%4,%5,%6,%7},{%8,%9},{%0,%1,%2,%3};"
        : "+r"(c[0]), "+r"(c[1]), "+r"(c[2]), "+r"(c[3])
        : "r"(a[0]), "r"(a[1]), "r"(a[2]), "r"(a[3]), "r"(b[0]), "r"(b[1]));
}

__global__ void zero_kernel() {
    size_t i = (size_t)blockIdx.x * blockDim.x + threadIdx.x;
    size_t stride = (size_t)gridDim.x * blockDim.x;
    const float4 z = make_float4(0.f, 0.f, 0.f, 0.f);
    for (size_t j = i; j < (size_t)Bq * H1n / 4; j += stride)
        reinterpret_cast<float4*>(g_mem1)[j] = z;
    for (size_t j = i; j < (size_t)Bq * H2n / 4; j += stride) {
        reinterpret_cast<float4*>(g_mem2)[j] = z;
        reinterpret_cast<float4*>(g_spk )[j] = z;
    }
}

// exact 3-way bf16 split
__global__ void split3_kernel(const float* __restrict__ src, size_t n, int which) {
    __nv_bfloat16 *h, *m, *l;
    if (which == 0) { h = g_w1h; m = g_w1m; l = g_w1l; }
    else            { h = g_x1;  m = g_x2;  l = g_x3;  }
    size_t i = (size_t)blockIdx.x * blockDim.x + threadIdx.x;
    size_t stride = (size_t)gridDim.x * blockDim.x;
    for (size_t j = i; j < n; j += stride) {
        float v = src[j];
        __nv_bfloat16 a = __float2bfloat16_rn(v);
        float r1 = v - __bfloat162float(a);
        __nv_bfloat16 b = __float2bfloat16_rn(r1);
        float r2 = r1 - __bfloat162float(b);
        h[j] = a; m[j] = b; l[j] = __float2bfloat16_rn(r2);
    }
}

// 4-window int8 split: w = i0*2^-9 + i1*2^-16 + i2*2^-23 + i3*2^-30 (+ residual <= 2^-31)
__global__ void split4_kernel(const float* __restrict__ src, size_t n, int which) {
    int8_t *p0, *p1, *p2, *p3;
    if (which == 0) { p0 = g_w1i0; p1 = g_w1i1; p2 = g_w1i2; p3 = g_w1i3; }
    else            { p0 = g_w2i0; p1 = g_w2i1; p2 = g_w2i2; p3 = g_w2i3; }
    size_t i = (size_t)blockIdx.x * blockDim.x + threadIdx.x;
    size_t stride = (size_t)gridDim.x * blockDim.x;
    for (size_t j = i; j < n; j += stride) {
        float v = src[j];
        float t0 = fminf(fmaxf(rintf(v * 0x1p9f), -127.f), 127.f);
        float r  = v - t0 * 0x1p-9f;
        float t1 = fminf(fmaxf(rintf(r * 0x1p16f), -127.f), 127.f);
        r -= t1 * 0x1p-16f;
        float t2 = fminf(fmaxf(rintf(r * 0x1p23f), -127.f), 127.f);
        r -= t2 * 0x1p-23f;
        float t3 = fminf(fmaxf(rintf(r * 0x1p30f), -127.f), 127.f);
        p0[j] = (int8_t)(int)t0;
        p1[j] = (int8_t)(int)t1;
        p2[j] = (int8_t)(int)t2;
        p3[j] = (int8_t)(int)t3;
    }
}

// ---------- t0 layer-1 GEMM: bf16, 6 significant split-pairs, pass-major ----------
__global__ __launch_bounds__(256, 1) void gemm_t0(const float* __restrict__ bias) {
    constexpr int KDIM = Dn, NDIM = H1n;
    constexpr int KC = KDIM / 64;          // 16
    constexpr int NPASS = 6;
    constexpr int NC = NPASS * KC;         // 96

    extern __shared__ char smraw[];
    const uint32_t smbase = smem_u32(smraw);
    const uint32_t tb = (smbase + 1023u) & ~1023u;

    const int tid  = threadIdx.x;
    const int wid  = tid >> 5;
    const int lane = tid & 31;
    const int wm = wid >> 2;
    const int wn = wid & 3;
    const int m0  = blockIdx.y * 128;
    const int n0c = blockIdx.x * 256;

    const __nv_bfloat16* Ap[NPASS] = {g_x1, g_x1, g_x1, g_x2, g_x2, g_x3};
    const __nv_bfloat16* Bp[NPASS] = {g_w1h, g_w1m, g_w1l, g_w1h, g_w1m, g_w1h};

    const int lrow = tid >> 3;
    const int lc16 = tid & 7;
    auto load_chunk = [&](int j) {
        const int p  = j >> 4;          // j / KC
        const int kc = j & 15;
        const uint32_t sa = tb + (j & 3) * T0_STAGE;
        const uint32_t sb = sa + T0_A;
        const __nv_bfloat16* As = Ap[p] + (size_t)m0  * KDIM + kc * 64 + lc16 * 8;
        const __nv_bfloat16* Bs = Bp[p] + (size_t)n0c * KDIM + kc * 64 + lc16 * 8;
        #pragma unroll
        for (int q = 0; q < 4; q++) {
            int row = lrow + q * 32;
            uint32_t off = (uint32_t)row * 128 + (uint32_t)((lc16 ^ (row & 7)) << 4);
            cp16(sa + off, As + (size_t)row * KDIM);
        }
        #pragma unroll
        for (int q = 0; q < 8; q++) {
            int row = lrow + q * 32;
            uint32_t off = (uint32_t)row * 128 + (uint32_t)((lc16 ^ (row & 7)) << 4);
            cp16(sb + off, Bs + (size_t)row * KDIM);
        }
        cp_commit();
    };

    const int aRow  = wm * 64 + (lane & 15);
    const uint32_t aXor = (uint32_t)(aRow & 7);
    uint32_t aob[4];
    #pragma unroll
    for (int f = 0; f < 4; f++) aob[f] = (uint32_t)(aRow + f * 16) * 128;
    const uint32_t aC16 = (uint32_t)(lane >> 4);
    const int bg     = lane >> 3;
    const int btile  = bg >> 1;
    const int bkhalf = bg & 1;
    const int bN     = wn * 64 + btile * 8 + (lane & 7);
    const uint32_t bXor = (uint32_t)(bN & 7);
    uint32_t bob[4];
    #pragma unroll
    for (int nf2 = 0; nf2 < 4; nf2++) bob[nf2] = (uint32_t)(bN + nf2 * 16) * 128;

    float acc[4][8][4];
    #pragma unroll
    for (int f = 0; f < 4; f++)
        #pragma unroll
        for (int nf = 0; nf < 8; nf++)
            #pragma unroll
            for (int q = 0; q < 4; q++) acc[f][nf][q] = 0.f;

    load_chunk(0); load_chunk(1); load_chunk(2);

    for (int i = 0; i < NC; i++) {
        cp_wait2();
        __syncthreads();
        const int j = i + 3;
        if (j < NC) load_chunk(j); else cp_commit();

        const uint32_t sa = tb + ((uint32_t)i & 3) * T0_STAGE;
        const uint32_t sb = sa + T0_A;
        #pragma unroll
        for (int ks = 0; ks < 4; ks++) {
            uint32_t af[4][4];
            #pragma unroll
            for (int f = 0; f < 4; f++) {
                uint32_t c16 = (uint32_t)(ks * 2) + aC16;
                ldsm4(af[f][0], af[f][1], af[f][2], af[f][3],
                      sa + aob[f] + ((c16 ^ aXor) << 4));
            }
            uint32_t bf[4][4];
            #pragma unroll
            for (int nf2 = 0; nf2 < 4; nf2++) {
                uint32_t c16 = (uint32_t)(ks * 2 + bkhalf);
                ldsm4(bf[nf2][0], bf[nf2][1], bf[nf2][2], bf[nf2][3],
                      sb + bob[nf2] + ((c16 ^ bXor) << 4));
            }
            #pragma unroll
            for (int f = 0; f < 4; f++)
                #pragma unroll
                for (int nf2 = 0; nf2 < 4; nf2++) {
                    mma16816(acc[f][nf2 * 2 + 0], af[f], &bf[nf2][0]);
                    mma16816(acc[f][nf2 * 2 + 1], af[f], &bf[nf2][2]);
                }
        }
    }

    const int r4  = lane >> 2;
    const int cp2 = (lane & 3) * 2;
    const int ncolw = n0c + wn * 64;
    #pragma unroll
    for (int f = 0; f < 4; f++) {
        #pragma unroll
        for (int h = 0; h < 2; h++) {
            const int m = m0 + wm * 64 + f * 16 + h * 8 + r4;
            float* memrow = g_mem1 + (size_t)m * NDIM + ncolw;
            int8_t* srow = g_s1b + (size_t)m * NDIM + ncolw;
            #pragma unroll
            for (int nf = 0; nf < 8; nf++) {
                const int nn = nf * 8 + cp2;
                float h0 = acc[f][nf][2 * h + 0] + bias[ncolw + nn];
                float h1 = acc[f][nf][2 * h + 1] + bias[ncolw + nn + 1];
                float2 mv = *reinterpret_cast<float2*>(memrow + nn);
                float n0v = BETA * mv.x + h0 - ((mv.x > THR) ? THR : 0.f);
                float n1v = BETA * mv.y + h1 - ((mv.y > THR) ? THR : 0.f);
                *reinterpret_cast<float2*>(memrow + nn) = make_float2(n0v, n1v);
                char2 sp;
                sp.x = (n0v > THR) ? 1 : 0;
                sp.y = (n1v > THR) ? 1 : 0;
                *reinterpret_cast<char2*>(srow + nn) = sp;
            }
        }
    }
}

// ---------- int8 spike GEMM: CTA 64x128, 2 CTAs/SM, 4-pass shift-chained ----------
template<int LAYER>
__global__ __launch_bounds__(256, 2) void gemm_i8(const float* __restrict__ bias) {
    constexpr int KDIM = (LAYER == 1) ? H2n : H1n;
    constexpr int NDIM = (LAYER == 1) ? H1n : H2n;
    constexpr bool SPK = (LAYER == 2);
    constexpr int KC = KDIM / 128;
    constexpr int NC = 4 * KC;

    extern __shared__ char smraw[];
    const uint32_t smbase = smem_u32(smraw);
    const uint32_t tb = (smbase + 1023u) & ~1023u;

    const int tid  = threadIdx.x;
    const int wid  = tid >> 5;
    const int lane = tid & 31;
    const int wm = wid >> 2;          // 0..1 (32 rows each)
    const int wn = wid & 3;           // 0..3 (32 cols each)
    const int m0  = blockIdx.y * 64;
    const int n0c = blockIdx.x * 128;

    const int8_t* A = (LAYER == 1) ? g_s2b : g_s1b;
    const int8_t* W[4];
    if (LAYER == 1) { W[0] = g_w1i0; W[1] = g_w1i1; W[2] = g_w1i2; W[3] = g_w1i3; }
    else            { W[0] = g_w2i0; W[1] = g_w2i1; W[2] = g_w2i2; W[3] = g_w2i3; }

    float* mem = (LAYER == 1) ? g_mem1 : g_mem2;
    int8_t* sout = (LAYER == 1) ? g_s1b : g_s2b;

    const int lrow = tid >> 3;          // 0..31
    const int lc16 = tid & 7;
    auto load_chunk = [&](int j) {
        const int p  = j / KC;
        const int kc = j - p * KC;
        const uint32_t sa = tb + (j & 3) * I8_STAGE;
        const uint32_t sb = sa + I8_A;
        const int8_t* As = A + (size_t)m0 * KDIM + kc * 128 + lc16 * 16;
        const int8_t* Bs = W[p] + (size_t)n0c * KDIM + kc * 128 + lc16 * 16;
        #pragma unroll
        for (int q = 0; q < 2; q++) {
            int row = lrow + q * 32;
            uint32_t off = (uint32_t)row * 128 + (uint32_t)((lc16 ^ (row & 7)) << 4);
            cp16(sa + off, As + (size_t)row * KDIM);
        }
        #pragma unroll
        for (int q = 0; q < 4; q++) {
            int row = lrow + q * 32;
            uint32_t off = (uint32_t)row * 128 + (uint32_t)((lc16 ^ (row & 7)) << 4);
            cp16(sb + off, Bs + (size_t)row * KDIM);
        }
        cp_commit();
    };

    const int aRow  = wm * 32 + (lane & 15);
    const uint32_t aXor = (uint32_t)(aRow & 7);
    uint32_t aob[2];
    #pragma unroll
    for (int f = 0; f < 2; f++) aob[f] = (uint32_t)(aRow + f * 16) * 128;
    const uint32_t aC16 = (uint32_t)(lane >> 4);
    const int bg     = lane >> 3;
    const int btile  = bg >> 1;
    const int bkhalf = bg & 1;
    const int bN     = wn * 32 + btile * 8 + (lane & 7);
    const uint32_t bXor = (uint32_t)(bN & 7);
    uint32_t bob[2];
    #pragma unroll
    for (int n2 = 0; n2 < 2; n2++) bob[n2] = (uint32_t)(bN + n2 * 16) * 128;

    int accA[2][4][4], accB[2][4][4];
    #pragma unroll
    for (int f = 0; f < 2; f++)
        #pragma unroll
        for (int o = 0; o < 4; o++)
            #pragma unroll
            for (int q = 0; q < 4; q++) { accA[f][o][q] = 0; accB[f][o][q] = 0; }

    load_chunk(0); load_chunk(1); load_chunk(2);

    for (int i = 0; i < NC; i++) {
        cp_wait2();
        __syncthreads();
        const int j = i + 3;
        if (j < NC) load_chunk(j); else cp_commit();

        const uint32_t sa = tb + ((uint32_t)i & 3) * I8_STAGE;
        const uint32_t sb = sa + I8_A;
        const int p = i / KC;

        auto run = [&](int (&acc)[2][4][4]) {
            #pragma unroll
            for (int ks = 0; ks < 4; ks++) {
                uint32_t af[2][4];
                #pragma unroll
                for (int f = 0; f < 2; f++) {
                    uint32_t c16 = (uint32_t)(ks * 2) + aC16;
                    ldsm4(af[f][0], af[f][1], af[f][2], af[f][3],
                          sa + aob[f] + ((c16 ^ aXor) << 4));
                }
                uint32_t bf[2][4];
                #pragma unroll
                for (int n2 = 0; n2 < 2; n2++) {
                    uint32_t c16 = (uint32_t)(ks * 2 + bkhalf);
                    ldsm4(bf[n2][0], bf[n2][1], bf[n2][2], bf[n2][3],
                          sb + bob[n2] + ((c16 ^ bXor) << 4));
                }
                #pragma unroll
                for (int f = 0; f < 2; f++)
                    #pragma unroll
                    for (int o = 0; o < 4; o++)
                        mma16832s8(acc[f][o], af[f], &bf[o >> 1][(o & 1) * 2]);
            }
        };
        if (p < 2) run(accA); else run(accB);

        if (i == KC - 1) {
            #pragma unroll
            for (int f = 0; f < 2; f++)
                #pragma unroll
                for (int o = 0; o < 4; o++)
                    #pragma unroll
                    for (int q = 0; q < 4; q++) accA[f][o][q] *= 128;
        }
        if (i == 3 * KC - 1) {
            #pragma unroll
            for (int f = 0; f < 2; f++)
                #pragma unroll
                for (int o = 0; o < 4; o++)
                    #pragma unroll
                    for (int q = 0; q < 4; q++) accB[f][o][q] *= 128;
        }
    }

    const int r4  = lane >> 2;
    const int cp2 = (lane & 3) * 2;
    const int ncolw = n0c + wn * 32;
    #pragma unroll
    for (int f = 0; f < 2; f++) {
        #pragma unroll
        for (int h = 0; h < 2; h++) {
            const int m = m0 + wm * 32 + f * 16 + h * 8 + r4;
            float* memrow = mem + (size_t)m * NDIM + ncolw;
            int8_t* srow = sout + (size_t)m * NDIM + ncolw;
            float* spkrow = g_spk + (size_t)m * NDIM + ncolw;
            #pragma unroll
            for (int o = 0; o < 4; o++) {
                const int nn = o * 8 + cp2;
                float hv[2];
                #pragma unroll
                for (int q = 0; q < 2; q++) {
                    int va = accA[f][o][2 * h + q];
                    int vb = accB[f][o][2 * h + q];
                    int ah = va >> 7, al = va - (ah << 7);
                    int bh = vb >> 7, bl = vb - (bh << 7);
                    hv[q] = bias[ncolw + nn + q]
                          + (float)ah * 0x1p-9f  + (float)al * 0x1p-16f
                          + (float)bh * 0x1p-23f + (float)bl * 0x1p-30f;
                }
                float2 mv = *reinterpret_cast<float2*>(memrow + nn);
                float n0v = BETA * mv.x + hv[0] - ((mv.x > THR) ? THR : 0.f);
                float n1v = BETA * mv.y + hv[1] - ((mv.y > THR) ? THR : 0.f);
                *reinterpret_cast<float2*>(memrow + nn) = make_float2(n0v, n1v);
                char2 sp;
                sp.x = (n0v > THR) ? 1 : 0;
                sp.y = (n1v > THR) ? 1 : 0;
                *reinterpret_cast<char2*>(srow + nn) = sp;
                if (SPK) {
                    float2 pk = *reinterpret_cast<float2*>(spkrow + nn);
                    pk.x += (n0v > THR) ? 1.f : 0.f;
                    pk.y += (n1v > THR) ? 1.f : 0.f;
                    *reinterpret_cast<float2*>(spkrow + nn) = pk;
                }
            }
        }
    }
}

__global__ __launch_bounds__(256) void out_kernel(
    const float* __restrict__ Wo,
    const float* __restrict__ bo,
    float* __restrict__ out)
{
    __shared__ float wsh[64 * 129];
    const int tid = threadIdx.x;
    const int c  = tid & 63;
    const int b  = blockIdx.x * 4 + (tid >> 6);

    float acc = 0.f;
    for (int k0 = 0; k0 < H2n; k0 += 128) {
        __syncthreads();
        #pragma unroll
        for (int it = 0; it < 8; it++) {
            int l  = tid + it * 256;
            int c2 = l >> 5;
            int kk = (l & 31) * 4;
            float4 w4 = *reinterpret_cast<const float4*>(&Wo[(size_t)c2 * H2n + k0 + kk]);
            wsh[c2 * 129 + kk + 0] = w4.x;
            wsh[c2 * 129 + kk + 1] = w4.y;
            wsh[c2 * 129 + kk + 2] = w4.z;
            wsh[c2 * 129 + kk + 3] = w4.w;
        }
        __syncthreads();
        const float* sp = &g_spk[(size_t)b * H2n + k0];
        #pragma unroll
        for (int k = 0; k < 128; k += 4) {
            float4 s4 = *reinterpret_cast<const float4*>(sp + k);
            acc = fmaf(s4.x, wsh[c * 129 + k + 0], acc);
            acc = fmaf(s4.y, wsh[c * 129 + k + 1], acc);
            acc = fmaf(s4.z, wsh[c * 129 + k + 2], acc);
            acc = fmaf(s4.w, wsh[c * 129 + k + 3], acc);
        }
    }
    out[(size_t)b * Cn + c] = acc * (1.0f / NSTEPS) + bo[c];
}

extern "C" void kernel_launch(void* const* d_in, const int* in_sizes, int n_in,
                              void* d_out, int out_size)
{
    const float* x  = (const float*)d_in[0];
    const float* W1 = (const float*)d_in[1];
    const float* b1 = (const float*)d_in[2];
    const float* W2 = (const float*)d_in[3];
    const float* b2 = (const float*)d_in[4];
    const float* Wo = (const float*)d_in[5];
    const float* bo = (const float*)d_in[6];
    float* out = (float*)d_out;

    cudaFuncSetAttribute(gemm_t0, cudaFuncAttributeMaxDynamicSharedMemorySize, SMEM_T0);
    cudaFuncSetAttribute(gemm_i8<1>, cudaFuncAttributeMaxDynamicSharedMemorySize, SMEM_I8);
    cudaFuncSetAttribute(gemm_i8<2>, cudaFuncAttributeMaxDynamicSharedMemorySize, SMEM_I8);

    zero_kernel<<<512, 256>>>();
    split3_kernel<<<512, 256>>>(W1, (size_t)H1n * Dn, 0);
    split3_kernel<<<512, 256>>>(x,  (size_t)Bq * Dn, 1);
    split4_kernel<<<512, 256>>>(W1, (size_t)H1n * Dn, 0);
    split4_kernel<<<512, 256>>>(W2, (size_t)H2n * H1n, 1);

    dim3 gt0(H1n / 256, Bq / 128);              // (8, 32)
    dim3 g1(H1n / 128, Bq / 64);                // (16, 64)
    dim3 g2(H2n / 128, Bq / 64);                // (8, 64)

    gemm_t0<<<gt0, 256, SMEM_T0>>>(b1);
    gemm_i8<2><<<g2, 256, SMEM_I8>>>(b2);
    for (int t = 1; t < NSTEPS; t++) {
        gemm_i8<1><<<g1, 256, SMEM_I8>>>(b1);
        gemm_i8<2><<<g2, 256, SMEM_I8>>>(b2);
    }
    out_kernel<<<Bq / 4, 256>>>(Wo, bo, out);
}

// round 12
// speedup vs baseline: 4.6385x; 1.2200x over previous
#include <cuda_runtime.h>
#include <cuda_bf16.h>
#include <cstdint>

#define DINL __device__ __forceinline__

namespace {
constexpr int Bq = 4096, Dn = 1024, H1n = 2048, H2n = 1024, Cn = 64, NSTEPS = 20;
constexpr float BETA = 0.9f, THR = 1.0f;
// t0 bf16 kernel: CTA 128x256, combined stage A(16K)+B(32K)
constexpr int T0_A = 128 * 128, T0_B = 256 * 128;
constexpr int T0_STAGE = T0_A + T0_B;               // 48 KB
constexpr int SMEM_T0 = 4 * T0_STAGE + 1024;        // ~193 KB
// int8 kernel: CTA 64x128, stage A(8K)+B(16K)
constexpr int I8_A = 64 * 128, I8_B = 128 * 128;
constexpr int I8_STAGE = I8_A + I8_B;               // 24 KB
constexpr int SMEM_I8 = 4 * I8_STAGE + 1024;        // ~97 KB -> 2 CTAs/SM
}

__device__ float g_mem1[(size_t)Bq * H1n];
__device__ float g_mem2[(size_t)Bq * H2n];
__device__ float g_spk [(size_t)Bq * H2n];
__device__ int8_t g_s1b[(size_t)Bq * H1n];
__device__ int8_t g_s2b[(size_t)Bq * H2n];
// bf16 splits (t0 only)
__device__ __nv_bfloat16 g_x1[(size_t)Bq * Dn];
__device__ __nv_bfloat16 g_x2[(size_t)Bq * Dn];
__device__ __nv_bfloat16 g_x3[(size_t)Bq * Dn];
__device__ __nv_bfloat16 g_w1h[(size_t)H1n * Dn];
__device__ __nv_bfloat16 g_w1m[(size_t)H1n * Dn];
__device__ __nv_bfloat16 g_w1l[(size_t)H1n * Dn];
// int8 3-window weight splits
__device__ int8_t g_w1i0[(size_t)H1n * Dn];
__device__ int8_t g_w1i1[(size_t)H1n * Dn];
__device__ int8_t g_w1i2[(size_t)H1n * Dn];
__device__ int8_t g_w2i0[(size_t)H2n * H1n];
__device__ int8_t g_w2i1[(size_t)H2n * H1n];
__device__ int8_t g_w2i2[(size_t)H2n * H1n];

DINL uint32_t smem_u32(const void* p) {
    uint32_t a;
    asm("{ .reg .u64 t; cvta.to.shared.u64 t, %1; cvt.u32.u64 %0, t; }" : "=r"(a) : "l"(p));
    return a;
}
DINL void cp16(uint32_t dst, const void* src) {
    asm volatile("cp.async.cg.shared.global [%0], [%1], 16;" :: "r"(dst), "l"(src));
}
DINL void cp_commit() { asm volatile("cp.async.commit_group;" ::: "memory"); }
DINL void cp_wait2()  { asm volatile("cp.async.wait_group 2;" ::: "memory"); }
DINL void ldsm4(uint32_t& r0, uint32_t& r1, uint32_t& r2, uint32_t& r3, uint32_t addr) {
    asm volatile("ldmatrix.sync.aligned.m8n8.x4.shared.b16 {%0,%1,%2,%3}, [%4];"
                 : "=r"(r0), "=r"(r1), "=r"(r2), "=r"(r3) : "r"(addr));
}
DINL void mma16816(float* c, const uint32_t* a, const uint32_t* b) {
    asm volatile(
        "mma.sync.aligned.m16n8k16.row.col.f32.bf16.bf16.f32 "
        "{%0,%1,%2,%3},{%4,%5,%6,%7},{%8,%9},{%0,%1,%2,%3};"
        : "+f"(c[0]), "+f"(c[1]), "+f"(c[2]), "+f"(c[3])
        : "r"(a[0]), "r"(a[1]), "r"(a[2]), "r"(a[3]), "r"(b[0]), "r"(b[1]));
}
DINL void mma16832s8(int* c, const uint32_t* a, const uint32_t* b) {
    asm volatile(
        "mma.sync.aligned.m16n8k32.row.col.s32.s8.s8.s32 "
        "{%0,%1,%2,%3},{%4,%5,%6,%7},{%8,%9},{%0,%1,%2,%3};"
        : "+r"(c[0]), "+r"(c[1]), "+r"(c[2]), "+r"(c[3])
        : "r"(a[0]), "r"(a[1]), "r"(a[2]), "r"(a[3]), "r"(b[0]), "r"(b[1]));
}

__global__ void zero_kernel() {
    size_t i = (size_t)blockIdx.x * blockDim.x + threadIdx.x;
    size_t stride = (size_t)gridDim.x * blockDim.x;
    const float4 z = make_float4(0.f, 0.f, 0.f, 0.f);
    for (size_t j = i; j < (size_t)Bq * H1n / 4; j += stride)
        reinterpret_cast<float4*>(g_mem1)[j] = z;
    for (size_t j = i; j < (size_t)Bq * H2n / 4; j += stride) {
        reinterpret_cast<float4*>(g_mem2)[j] = z;
        reinterpret_cast<float4*>(g_spk )[j] = z;
    }
}

// exact 3-way bf16 split
__global__ void split3_kernel(const float* __restrict__ src, size_t n, int which) {
    __nv_bfloat16 *h, *m, *l;
    if (which == 0) { h = g_w1h; m = g_w1m; l = g_w1l; }
    else            { h = g_x1;  m = g_x2;  l = g_x3;  }
    size_t i = (size_t)blockIdx.x * blockDim.x + threadIdx.x;
    size_t stride = (size_t)gridDim.x * blockDim.x;
    for (size_t j = i; j < n; j += stride) {
        float v = src[j];
        __nv_bfloat16 a = __float2bfloat16_rn(v);
        float r1 = v - __bfloat162float(a);
        __nv_bfloat16 b = __float2bfloat16_rn(r1);
        float r2 = r1 - __bfloat162float(b);
        h[j] = a; m[j] = b; l[j] = __float2bfloat16_rn(r2);
    }
}

// 3-window int8 split: w = i0*2^-9 + i1*2^-16 + i2*2^-23 (+ residual <= 2^-24)
__global__ void split4_kernel(const float* __restrict__ src, size_t n, int which) {
    int8_t *p0, *p1, *p2;
    if (which == 0) { p0 = g_w1i0; p1 = g_w1i1; p2 = g_w1i2; }
    else            { p0 = g_w2i0; p1 = g_w2i1; p2 = g_w2i2; }
    size_t i = (size_t)blockIdx.x * blockDim.x + threadIdx.x;
    size_t stride = (size_t)gridDim.x * blockDim.x;
    for (size_t j = i; j < n; j += stride) {
        float v = src[j];
        float t0 = fminf(fmaxf(rintf(v * 0x1p9f), -127.f), 127.f);
        float r  = v - t0 * 0x1p-9f;
        float t1 = fminf(fmaxf(rintf(r * 0x1p16f), -127.f), 127.f);
        r -= t1 * 0x1p-16f;
        float t2 = fminf(fmaxf(rintf(r * 0x1p23f), -127.f), 127.f);
        p0[j] = (int8_t)(int)t0;
        p1[j] = (int8_t)(int)t1;
        p2[j] = (int8_t)(int)t2;
    }
}

// ---------- t0 layer-1 GEMM: bf16, 6 significant split-pairs, pass-major ----------
__global__ __launch_bounds__(256, 1) void gemm_t0(const float* __restrict__ bias) {
    constexpr int KDIM = Dn, NDIM = H1n;
    constexpr int KC = KDIM / 64;          // 16
    constexpr int NPASS = 6;
    constexpr int NC = NPASS * KC;         // 96

    extern __shared__ char smraw[];
    const uint32_t smbase = smem_u32(smraw);
    const uint32_t tb = (smbase + 1023u) & ~1023u;

    const int tid  = threadIdx.x;
    const int wid  = tid >> 5;
    const int lane = tid & 31;
    const int wm = wid >> 2;
    const int wn = wid & 3;
    const int m0  = blockIdx.y * 128;
    const int n0c = blockIdx.x * 256;

    const __nv_bfloat16* Ap[NPASS] = {g_x1, g_x1, g_x1, g_x2, g_x2, g_x3};
    const __nv_bfloat16* Bp[NPASS] = {g_w1h, g_w1m, g_w1l, g_w1h, g_w1m, g_w1h};

    const int lrow = tid >> 3;
    const int lc16 = tid & 7;
    auto load_chunk = [&](int j) {
        const int p  = j >> 4;          // j / KC
        const int kc = j & 15;
        const uint32_t sa = tb + (j & 3) * T0_STAGE;
        const uint32_t sb = sa + T0_A;
        const __nv_bfloat16* As = Ap[p] + (size_t)m0  * KDIM + kc * 64 + lc16 * 8;
        const __nv_bfloat16* Bs = Bp[p] + (size_t)n0c * KDIM + kc * 64 + lc16 * 8;
        #pragma unroll
        for (int q = 0; q < 4; q++) {
            int row = lrow + q * 32;
            uint32_t off = (uint32_t)row * 128 + (uint32_t)((lc16 ^ (row & 7)) << 4);
            cp16(sa + off, As + (size_t)row * KDIM);
        }
        #pragma unroll
        for (int q = 0; q < 8; q++) {
            int row = lrow + q * 32;
            uint32_t off = (uint32_t)row * 128 + (uint32_t)((lc16 ^ (row & 7)) << 4);
            cp16(sb + off, Bs + (size_t)row * KDIM);
        }
        cp_commit();
    };

    const int aRow  = wm * 64 + (lane & 15);
    const uint32_t aXor = (uint32_t)(aRow & 7);
    uint32_t aob[4];
    #pragma unroll
    for (int f = 0; f < 4; f++) aob[f] = (uint32_t)(aRow + f * 16) * 128;
    const uint32_t aC16 = (uint32_t)(lane >> 4);
    const int bg     = lane >> 3;
    const int btile  = bg >> 1;
    const int bkhalf = bg & 1;
    const int bN     = wn * 64 + btile * 8 + (lane & 7);
    const uint32_t bXor = (uint32_t)(bN & 7);
    uint32_t bob[4];
    #pragma unroll
    for (int nf2 = 0; nf2 < 4; nf2++) bob[nf2] = (uint32_t)(bN + nf2 * 16) * 128;

    float acc[4][8][4];
    #pragma unroll
    for (int f = 0; f < 4; f++)
        #pragma unroll
        for (int nf = 0; nf < 8; nf++)
            #pragma unroll
            for (int q = 0; q < 4; q++) acc[f][nf][q] = 0.f;

    load_chunk(0); load_chunk(1); load_chunk(2);

    for (int i = 0; i < NC; i++) {
        cp_wait2();
        __syncthreads();
        const int j = i + 3;
        if (j < NC) load_chunk(j); else cp_commit();

        const uint32_t sa = tb + ((uint32_t)i & 3) * T0_STAGE;
        const uint32_t sb = sa + T0_A;
        #pragma unroll
        for (int ks = 0; ks < 4; ks++) {
            uint32_t af[4][4];
            #pragma unroll
            for (int f = 0; f < 4; f++) {
                uint32_t c16 = (uint32_t)(ks * 2) + aC16;
                ldsm4(af[f][0], af[f][1], af[f][2], af[f][3],
                      sa + aob[f] + ((c16 ^ aXor) << 4));
            }
            uint32_t bf[4][4];
            #pragma unroll
            for (int nf2 = 0; nf2 < 4; nf2++) {
                uint32_t c16 = (uint32_t)(ks * 2 + bkhalf);
                ldsm4(bf[nf2][0], bf[nf2][1], bf[nf2][2], bf[nf2][3],
                      sb + bob[nf2] + ((c16 ^ bXor) << 4));
            }
            #pragma unroll
            for (int f = 0; f < 4; f++)
                #pragma unroll
                for (int nf2 = 0; nf2 < 4; nf2++) {
                    mma16816(acc[f][nf2 * 2 + 0], af[f], &bf[nf2][0]);
                    mma16816(acc[f][nf2 * 2 + 1], af[f], &bf[nf2][2]);
                }
        }
    }

    const int r4  = lane >> 2;
    const int cp2 = (lane & 3) * 2;
    const int ncolw = n0c + wn * 64;
    #pragma unroll
    for (int f = 0; f < 4; f++) {
        #pragma unroll
        for (int h = 0; h < 2; h++) {
            const int m = m0 + wm * 64 + f * 16 + h * 8 + r4;
            float* memrow = g_mem1 + (size_t)m * NDIM + ncolw;
            int8_t* srow = g_s1b + (size_t)m * NDIM + ncolw;
            #pragma unroll
            for (int nf = 0; nf < 8; nf++) {
                const int nn = nf * 8 + cp2;
                float h0 = acc[f][nf][2 * h + 0] + bias[ncolw + nn];
                float h1 = acc[f][nf][2 * h + 1] + bias[ncolw + nn + 1];
                float2 mv = *reinterpret_cast<float2*>(memrow + nn);
                float n0v = BETA * mv.x + h0 - ((mv.x > THR) ? THR : 0.f);
                float n1v = BETA * mv.y + h1 - ((mv.y > THR) ? THR : 0.f);
                *reinterpret_cast<float2*>(memrow + nn) = make_float2(n0v, n1v);
                char2 sp;
                sp.x = (n0v > THR) ? 1 : 0;
                sp.y = (n1v > THR) ? 1 : 0;
                *reinterpret_cast<char2*>(srow + nn) = sp;
            }
        }
    }
}

// ---------- int8 spike GEMM: CTA 64x128, 2 CTAs/SM, 3-pass shift-chained ----------
template<int LAYER>
__global__ __launch_bounds__(256, 2) void gemm_i8(const float* __restrict__ bias) {
    constexpr int KDIM = (LAYER == 1) ? H2n : H1n;
    constexpr int NDIM = (LAYER == 1) ? H1n : H2n;
    constexpr bool SPK = (LAYER == 2);
    constexpr int KC = KDIM / 128;
    constexpr int NC = 3 * KC;

    extern __shared__ char smraw[];
    const uint32_t smbase = smem_u32(smraw);
    const uint32_t tb = (smbase + 1023u) & ~1023u;

    const int tid  = threadIdx.x;
    const int wid  = tid >> 5;
    const int lane = tid & 31;
    const int wm = wid >> 2;          // 0..1 (32 rows each)
    const int wn = wid & 3;           // 0..3 (32 cols each)
    const int m0  = blockIdx.y * 64;
    const int n0c = blockIdx.x * 128;

    const int8_t* A = (LAYER == 1) ? g_s2b : g_s1b;
    const int8_t* W[3];
    if (LAYER == 1) { W[0] = g_w1i0; W[1] = g_w1i1; W[2] = g_w1i2; }
    else            { W[0] = g_w2i0; W[1] = g_w2i1; W[2] = g_w2i2; }

    float* mem = (LAYER == 1) ? g_mem1 : g_mem2;
    int8_t* sout = (LAYER == 1) ? g_s1b : g_s2b;

    const int lrow = tid >> 3;          // 0..31
    const int lc16 = tid & 7;
    auto load_chunk = [&](int j) {
        const int p  = j / KC;
        const int kc = j - p * KC;
        const uint32_t sa = tb + (j & 3) * I8_STAGE;
        const uint32_t sb = sa + I8_A;
        const int8_t* As = A + (size_t)m0 * KDIM + kc * 128 + lc16 * 16;
        const int8_t* Bs = W[p] + (size_t)n0c * KDIM + kc * 128 + lc16 * 16;
        #pragma unroll
        for (int q = 0; q < 2; q++) {
            int row = lrow + q * 32;
            uint32_t off = (uint32_t)row * 128 + (uint32_t)((lc16 ^ (row & 7)) << 4);
            cp16(sa + off, As + (size_t)row * KDIM);
        }
        #pragma unroll
        for (int q = 0; q < 4; q++) {
            int row = lrow + q * 32;
            uint32_t off = (uint32_t)row * 128 + (uint32_t)((lc16 ^ (row & 7)) << 4);
            cp16(sb + off, Bs + (size_t)row * KDIM);
        }
        cp_commit();
    };

    const int aRow  = wm * 32 + (lane & 15);
    const uint32_t aXor = (uint32_t)(aRow & 7);
    uint32_t aob[2];
    #pragma unroll
    for (int f = 0; f < 2; f++) aob[f] = (uint32_t)(aRow + f * 16) * 128;
    const uint32_t aC16 = (uint32_t)(lane >> 4);
    const int bg     = lane >> 3;
    const int btile  = bg >> 1;
    const int bkhalf = bg & 1;
    const int bN     = wn * 32 + btile * 8 + (lane & 7);
    const uint32_t bXor = (uint32_t)(bN & 7);
    uint32_t bob[2];
    #pragma unroll
    for (int n2 = 0; n2 < 2; n2++) bob[n2] = (uint32_t)(bN + n2 * 16) * 128;

    int accA[2][4][4], accB[2][4][4];
    #pragma unroll
    for (int f = 0; f < 2; f++)
        #pragma unroll
        for (int o = 0; o < 4; o++)
            #pragma unroll
            for (int q = 0; q < 4; q++) { accA[f][o][q] = 0; accB[f][o][q] = 0; }

    load_chunk(0); load_chunk(1); load_chunk(2);

    for (int i = 0; i < NC; i++) {
        cp_wait2();
        __syncthreads();
        const int j = i + 3;
        if (j < NC) load_chunk(j); else cp_commit();

        const uint32_t sa = tb + ((uint32_t)i & 3) * I8_STAGE;
        const uint32_t sb = sa + I8_A;
        const int p = i / KC;

        auto run = [&](int (&acc)[2][4][4]) {
            #pragma unroll
            for (int ks = 0; ks < 4; ks++) {
                uint32_t af[2][4];
                #pragma unroll
                for (int f = 0; f < 2; f++) {
                    uint32_t c16 = (uint32_t)(ks * 2) + aC16;
                    ldsm4(af[f][0], af[f][1], af[f][2], af[f][3],
                          sa + aob[f] + ((c16 ^ aXor) << 4));
                }
                uint32_t bf[2][4];
                #pragma unroll
                for (int n2 = 0; n2 < 2; n2++) {
                    uint32_t c16 = (uint32_t)(ks * 2 + bkhalf);
                    ldsm4(bf[n2][0], bf[n2][1], bf[n2][2], bf[n2][3],
                          sb + bob[n2] + ((c16 ^ bXor) << 4));
                }
                #pragma unroll
                for (int f = 0; f < 2; f++)
                    #pragma unroll
                    for (int o = 0; o < 4; o++)
                        mma16832s8(acc[f][o], af[f], &bf[o >> 1][(o & 1) * 2]);
            }
        };
        // passes 0,1 -> accA (shift-chained); pass 2 -> accB
        if (p < 2) run(accA); else run(accB);

        if (i == KC - 1) {
            #pragma unroll
            for (int f = 0; f < 2; f++)
                #pragma unroll
                for (int o = 0; o < 4; o++)
                    #pragma unroll
                    for (int q = 0; q < 4; q++) accA[f][o][q] *= 128;
        }
    }

    // epilogue: exact recombination + LIF
    // accA = 128*sum(i0) + sum(i1); accB = sum(i2)
    const int r4  = lane >> 2;
    const int cp2 = (lane & 3) * 2;
    const int ncolw = n0c + wn * 32;
    #pragma unroll
    for (int f = 0; f < 2; f++) {
        #pragma unroll
        for (int h = 0; h < 2; h++) {
            const int m = m0 + wm * 32 + f * 16 + h * 8 + r4;
            float* memrow = mem + (size_t)m * NDIM + ncolw;
            int8_t* srow = sout + (size_t)m * NDIM + ncolw;
            float* spkrow = g_spk + (size_t)m * NDIM + ncolw;
            #pragma unroll
            for (int o = 0; o < 4; o++) {
                const int nn = o * 8 + cp2;
                float hv[2];
                #pragma unroll
                for (int q = 0; q < 2; q++) {
                    int va = accA[f][o][2 * h + q];
                    int vb = accB[f][o][2 * h + q];
                    int ah = va >> 7, al = va - (ah << 7);
                    hv[q] = bias[ncolw + nn + q]
                          + (float)ah * 0x1p-9f + (float)al * 0x1p-16f
                          + (float)vb * 0x1p-23f;
                }
                float2 mv = *reinterpret_cast<float2*>(memrow + nn);
                float n0v = BETA * mv.x + hv[0] - ((mv.x > THR) ? THR : 0.f);
                float n1v = BETA * mv.y + hv[1] - ((mv.y > THR) ? THR : 0.f);
                *reinterpret_cast<float2*>(memrow + nn) = make_float2(n0v, n1v);
                char2 sp;
                sp.x = (n0v > THR) ? 1 : 0;
                sp.y = (n1v > THR) ? 1 : 0;
                *reinterpret_cast<char2*>(srow + nn) = sp;
                if (SPK) {
                    float2 pk = *reinterpret_cast<float2*>(spkrow + nn);
                    pk.x += (n0v > THR) ? 1.f : 0.f;
                    pk.y += (n1v > THR) ? 1.f : 0.f;
                    *reinterpret_cast<float2*>(spkrow + nn) = pk;
                }
            }
        }
    }
}

__global__ __launch_bounds__(256) void out_kernel(
    const float* __restrict__ Wo,
    const float* __restrict__ bo,
    float* __restrict__ out)
{
    __shared__ float wsh[64 * 129];
    const int tid = threadIdx.x;
    const int c  = tid & 63;
    const int b  = blockIdx.x * 4 + (tid >> 6);

    float acc = 0.f;
    for (int k0 = 0; k0 < H2n; k0 += 128) {
        __syncthreads();
        #pragma unroll
        for (int it = 0; it < 8; it++) {
            int l  = tid + it * 256;
            int c2 = l >> 5;
            int kk = (l & 31) * 4;
            float4 w4 = *reinterpret_cast<const float4*>(&Wo[(size_t)c2 * H2n + k0 + kk]);
            wsh[c2 * 129 + kk + 0] = w4.x;
            wsh[c2 * 129 + kk + 1] = w4.y;
            wsh[c2 * 129 + kk + 2] = w4.z;
            wsh[c2 * 129 + kk + 3] = w4.w;
        }
        __syncthreads();
        const float* sp = &g_spk[(size_t)b * H2n + k0];
        #pragma unroll
        for (int k = 0; k < 128; k += 4) {
            float4 s4 = *reinterpret_cast<const float4*>(sp + k);
            acc = fmaf(s4.x, wsh[c * 129 + k + 0], acc);
            acc = fmaf(s4.y, wsh[c * 129 + k + 1], acc);
            acc = fmaf(s4.z, wsh[c * 129 + k + 2], acc);
            acc = fmaf(s4.w, wsh[c * 129 + k + 3], acc);
        }
    }
    out[(size_t)b * Cn + c] = acc * (1.0f / NSTEPS) + bo[c];
}

extern "C" void kernel_launch(void* const* d_in, const int* in_sizes, int n_in,
                              void* d_out, int out_size)
{
    const float* x  = (const float*)d_in[0];
    const float* W1 = (const float*)d_in[1];
    const float* b1 = (const float*)d_in[2];
    const float* W2 = (const float*)d_in[3];
    const float* b2 = (const float*)d_in[4];
    const float* Wo = (const float*)d_in[5];
    const float* bo = (const float*)d_in[6];
    float* out = (float*)d_out;

    cudaFuncSetAttribute(gemm_t0, cudaFuncAttributeMaxDynamicSharedMemorySize, SMEM_T0);
    cudaFuncSetAttribute(gemm_i8<1>, cudaFuncAttributeMaxDynamicSharedMemorySize, SMEM_I8);
    cudaFuncSetAttribute(gemm_i8<2>, cudaFuncAttributeMaxDynamicSharedMemorySize, SMEM_I8);

    zero_kernel<<<512, 256>>>();
    split3_kernel<<<512, 256>>>(W1, (size_t)H1n * Dn, 0);
    split3_kernel<<<512, 256>>>(x,  (size_t)Bq * Dn, 1);
    split4_kernel<<<512, 256>>>(W1, (size_t)H1n * Dn, 0);
    split4_kernel<<<512, 256>>>(W2, (size_t)H2n * H1n, 1);

    dim3 gt0(H1n / 256, Bq / 128);              // (8, 32)
    dim3 g1(H1n / 128, Bq / 64);                // (16, 64)
    dim3 g2(H2n / 128, Bq / 64);                // (8, 64)

    gemm_t0<<<gt0, 256, SMEM_T0>>>(b1);
    gemm_i8<2><<<g2, 256, SMEM_I8>>>(b2);
    for (int t = 1; t < NSTEPS; t++) {
        gemm_i8<1><<<g1, 256, SMEM_I8>>>(b1);
        gemm_i8<2><<<g2, 256, SMEM_I8>>>(b2);
    }
    out_kernel<<<Bq / 4, 256>>>(Wo, bo, out);
}

// round 14
// speedup vs baseline: 4.7189x; 1.0173x over previous
#include <cuda_runtime.h>
#include <cuda_bf16.h>
#include <cstdint>

#define DINL __device__ __forceinline__

namespace {
constexpr int Bq = 4096, Dn = 1024, H1n = 2048, H2n = 1024, Cn = 64, NSTEPS = 20;
constexpr float BETA = 0.9f, THR = 1.0f;
// t0 bf16 kernel: CTA 128x256, combined stage A(16K)+B(32K)
constexpr int T0_A = 128 * 128, T0_B = 256 * 128;
constexpr int T0_STAGE = T0_A + T0_B;               // 48 KB
constexpr int SMEM_T0 = 4 * T0_STAGE + 1024;        // ~193 KB
// int8 kernel: CTA 128x128, stage A(16K)+B(16K), 3-stage ring
constexpr int I8_A = 128 * 128, I8_B = 128 * 128;
constexpr int I8_STAGE = I8_A + I8_B;               // 32 KB
constexpr int SMEM_I8 = 3 * I8_STAGE + 1024;        // ~97 KB -> 2 CTAs/SM
}

__device__ float g_mem1[(size_t)Bq * H1n];
__device__ float g_mem2[(size_t)Bq * H2n];
__device__ float g_spk [(size_t)Bq * H2n];
__device__ int8_t g_s1b[(size_t)Bq * H1n];
__device__ int8_t g_s2b[(size_t)Bq * H2n];
// bf16 splits (t0 only)
__device__ __nv_bfloat16 g_x1[(size_t)Bq * Dn];
__device__ __nv_bfloat16 g_x2[(size_t)Bq * Dn];
__device__ __nv_bfloat16 g_x3[(size_t)Bq * Dn];
__device__ __nv_bfloat16 g_w1h[(size_t)H1n * Dn];
__device__ __nv_bfloat16 g_w1m[(size_t)H1n * Dn];
__device__ __nv_bfloat16 g_w1l[(size_t)H1n * Dn];
// int8 3-window weight splits
__device__ int8_t g_w1i0[(size_t)H1n * Dn];
__device__ int8_t g_w1i1[(size_t)H1n * Dn];
__device__ int8_t g_w1i2[(size_t)H1n * Dn];
__device__ int8_t g_w2i0[(size_t)H2n * H1n];
__device__ int8_t g_w2i1[(size_t)H2n * H1n];
__device__ int8_t g_w2i2[(size_t)H2n * H1n];

DINL uint32_t smem_u32(const void* p) {
    uint32_t a;
    asm("{ .reg .u64 t; cvta.to.shared.u64 t, %1; cvt.u32.u64 %0, t; }" : "=r"(a) : "l"(p));
    return a;
}
DINL void cp16(uint32_t dst, const void* src) {
    asm volatile("cp.async.cg.shared.global [%0], [%1], 16;" :: "r"(dst), "l"(src));
}
DINL void cp_commit() { asm volatile("cp.async.commit_group;" ::: "memory"); }
DINL void cp_wait2()  { asm volatile("cp.async.wait_group 2;" ::: "memory"); }
DINL void cp_wait1()  { asm volatile("cp.async.wait_group 1;" ::: "memory"); }
DINL void cp_wait0()  { asm volatile("cp.async.wait_group 0;" ::: "memory"); }
DINL void ldsm4(uint32_t& r0, uint32_t& r1, uint32_t& r2, uint32_t& r3, uint32_t addr) {
    asm volatile("ldmatrix.sync.aligned.m8n8.x4.shared.b16 {%0,%1,%2,%3}, [%4];"
                 : "=r"(r0), "=r"(r1), "=r"(r2), "=r"(r3) : "r"(addr));
}
DINL void mma16816(float* c, const uint32_t* a, const uint32_t* b) {
    asm volatile(
        "mma.sync.aligned.m16n8k16.row.col.f32.bf16.bf16.f32 "
        "{%0,%1,%2,%3},{%4,%5,%6,%7},{%8,%9},{%0,%1,%2,%3};"
        : "+f"(c[0]), "+f"(c[1]), "+f"(c[2]), "+f"(c[3])
        : "r"(a[0]), "r"(a[1]), "r"(a[2]), "r"(a[3]), "r"(b[0]), "r"(b[1]));
}
DINL void mma16832s8(int* c, const uint32_t* a, const uint32_t* b) {
    asm volatile(
        "mma.sync.aligned.m16n8k32.row.col.s32.s8.s8.s32 "
        "{%0,%1,%2,%3},{%4,%5,%6,%7},{%8,%9},{%0,%1,%2,%3};"
        : "+r"(c[0]), "+r"(c[1]), "+r"(c[2]), "+r"(c[3])
        : "r"(a[0]), "r"(a[1]), "r"(a[2]), "r"(a[3]), "r"(b[0]), "r"(b[1]));
}

__global__ void zero_kernel() {
    size_t i = (size_t)blockIdx.x * blockDim.x + threadIdx.x;
    size_t stride = (size_t)gridDim.x * blockDim.x;
    const float4 z = make_float4(0.f, 0.f, 0.f, 0.f);
    for (size_t j = i; j < (size_t)Bq * H1n / 4; j += stride)
        reinterpret_cast<float4*>(g_mem1)[j] = z;
    for (size_t j = i; j < (size_t)Bq * H2n / 4; j += stride) {
        reinterpret_cast<float4*>(g_mem2)[j] = z;
        reinterpret_cast<float4*>(g_spk )[j] = z;
    }
}

// exact 3-way bf16 split
__global__ void split3_kernel(const float* __restrict__ src, size_t n, int which) {
    __nv_bfloat16 *h, *m, *l;
    if (which == 0) { h = g_w1h; m = g_w1m; l = g_w1l; }
    else            { h = g_x1;  m = g_x2;  l = g_x3;  }
    size_t i = (size_t)blockIdx.x * blockDim.x + threadIdx.x;
    size_t stride = (size_t)gridDim.x * blockDim.x;
    for (size_t j = i; j < n; j += stride) {
        float v = src[j];
        __nv_bfloat16 a = __float2bfloat16_rn(v);
        float r1 = v - __bfloat162float(a);
        __nv_bfloat16 b = __float2bfloat16_rn(r1);
        float r2 = r1 - __bfloat162float(b);
        h[j] = a; m[j] = b; l[j] = __float2bfloat16_rn(r2);
    }
}

// 3-window int8 split: w = i0*2^-9 + i1*2^-16 + i2*2^-23 (+ residual <= 2^-24)
__global__ void split4_kernel(const float* __restrict__ src, size_t n, int which) {
    int8_t *p0, *p1, *p2;
    if (which == 0) { p0 = g_w1i0; p1 = g_w1i1; p2 = g_w1i2; }
    else            { p0 = g_w2i0; p1 = g_w2i1; p2 = g_w2i2; }
    size_t i = (size_t)blockIdx.x * blockDim.x + threadIdx.x;
    size_t stride = (size_t)gridDim.x * blockDim.x;
    for (size_t j = i; j < n; j += stride) {
        float v = src[j];
        float t0 = fminf(fmaxf(rintf(v * 0x1p9f), -127.f), 127.f);
        float r  = v - t0 * 0x1p-9f;
        float t1 = fminf(fmaxf(rintf(r * 0x1p16f), -127.f), 127.f);
        r -= t1 * 0x1p-16f;
        float t2 = fminf(fmaxf(rintf(r * 0x1p23f), -127.f), 127.f);
        p0[j] = (int8_t)(int)t0;
        p1[j] = (int8_t)(int)t1;
        p2[j] = (int8_t)(int)t2;
    }
}

// ---------- t0 layer-1 GEMM: bf16, 6 significant split-pairs, pass-major ----------
__global__ __launch_bounds__(256, 1) void gemm_t0(const float* __restrict__ bias) {
    constexpr int KDIM = Dn, NDIM = H1n;
    constexpr int KC = KDIM / 64;          // 16
    constexpr int NPASS = 6;
    constexpr int NC = NPASS * KC;         // 96

    extern __shared__ char smraw[];
    const uint32_t smbase = smem_u32(smraw);
    const uint32_t tb = (smbase + 1023u) & ~1023u;

    const int tid  = threadIdx.x;
    const int wid  = tid >> 5;
    const int lane = tid & 31;
    const int wm = wid >> 2;
    const int wn = wid & 3;
    const int m0  = blockIdx.y * 128;
    const int n0c = blockIdx.x * 256;

    const __nv_bfloat16* Ap[NPASS] = {g_x1, g_x1, g_x1, g_x2, g_x2, g_x3};
    const __nv_bfloat16* Bp[NPASS] = {g_w1h, g_w1m, g_w1l, g_w1h, g_w1m, g_w1h};

    const int lrow = tid >> 3;
    const int lc16 = tid & 7;
    auto load_chunk = [&](int j) {
        const int p  = j >> 4;
        const int kc = j & 15;
        const uint32_t sa = tb + (j & 3) * T0_STAGE;
        const uint32_t sb = sa + T0_A;
        const __nv_bfloat16* As = Ap[p] + (size_t)m0  * KDIM + kc * 64 + lc16 * 8;
        const __nv_bfloat16* Bs = Bp[p] + (size_t)n0c * KDIM + kc * 64 + lc16 * 8;
        #pragma unroll
        for (int q = 0; q < 4; q++) {
            int row = lrow + q * 32;
            uint32_t off = (uint32_t)row * 128 + (uint32_t)((lc16 ^ (row & 7)) << 4);
            cp16(sa + off, As + (size_t)row * KDIM);
        }
        #pragma unroll
        for (int q = 0; q < 8; q++) {
            int row = lrow + q * 32;
            uint32_t off = (uint32_t)row * 128 + (uint32_t)((lc16 ^ (row & 7)) << 4);
            cp16(sb + off, Bs + (size_t)row * KDIM);
        }
        cp_commit();
    };

    const int aRow  = wm * 64 + (lane & 15);
    const uint32_t aXor = (uint32_t)(aRow & 7);
    uint32_t aob[4];
    #pragma unroll
    for (int f = 0; f < 4; f++) aob[f] = (uint32_t)(aRow + f * 16) * 128;
    const uint32_t aC16 = (uint32_t)(lane >> 4);
    const int bg     = lane >> 3;
    const int btile  = bg >> 1;
    const int bkhalf = bg & 1;
    const int bN     = wn * 64 + btile * 8 + (lane & 7);
    const uint32_t bXor = (uint32_t)(bN & 7);
    uint32_t bob[4];
    #pragma unroll
    for (int nf2 = 0; nf2 < 4; nf2++) bob[nf2] = (uint32_t)(bN + nf2 * 16) * 128;

    float acc[4][8][4];
    #pragma unroll
    for (int f = 0; f < 4; f++)
        #pragma unroll
        for (int nf = 0; nf < 8; nf++)
            #pragma unroll
            for (int q = 0; q < 4; q++) acc[f][nf][q] = 0.f;

    load_chunk(0); load_chunk(1); load_chunk(2);

    for (int i = 0; i < NC; i++) {
        cp_wait2();
        __syncthreads();
        const int j = i + 3;
        if (j < NC) load_chunk(j); else cp_commit();

        const uint32_t sa = tb + ((uint32_t)i & 3) * T0_STAGE;
        const uint32_t sb = sa + T0_A;
        #pragma unroll
        for (int ks = 0; ks < 4; ks++) {
            uint32_t af[4][4];
            #pragma unroll
            for (int f = 0; f < 4; f++) {
                uint32_t c16 = (uint32_t)(ks * 2) + aC16;
                ldsm4(af[f][0], af[f][1], af[f][2], af[f][3],
                      sa + aob[f] + ((c16 ^ aXor) << 4));
            }
            uint32_t bf[4][4];
            #pragma unroll
            for (int nf2 = 0; nf2 < 4; nf2++) {
                uint32_t c16 = (uint32_t)(ks * 2 + bkhalf);
                ldsm4(bf[nf2][0], bf[nf2][1], bf[nf2][2], bf[nf2][3],
                      sb + bob[nf2] + ((c16 ^ bXor) << 4));
            }
            #pragma unroll
            for (int f = 0; f < 4; f++)
                #pragma unroll
                for (int nf2 = 0; nf2 < 4; nf2++) {
                    mma16816(acc[f][nf2 * 2 + 0], af[f], &bf[nf2][0]);
                    mma16816(acc[f][nf2 * 2 + 1], af[f], &bf[nf2][2]);
                }
        }
    }

    const int r4  = lane >> 2;
    const int cp2 = (lane & 3) * 2;
    const int ncolw = n0c + wn * 64;
    #pragma unroll
    for (int f = 0; f < 4; f++) {
        #pragma unroll
        for (int h = 0; h < 2; h++) {
            const int m = m0 + wm * 64 + f * 16 + h * 8 + r4;
            float* memrow = g_mem1 + (size_t)m * NDIM + ncolw;
            int8_t* srow = g_s1b + (size_t)m * NDIM + ncolw;
            #pragma unroll
            for (int nf = 0; nf < 8; nf++) {
                const int nn = nf * 8 + cp2;
                float h0 = acc[f][nf][2 * h + 0] + bias[ncolw + nn];
                float h1 = acc[f][nf][2 * h + 1] + bias[ncolw + nn + 1];
                float2 mv = *reinterpret_cast<float2*>(memrow + nn);
                float n0v = BETA * mv.x + h0 - ((mv.x > THR) ? THR : 0.f);
                float n1v = BETA * mv.y + h1 - ((mv.y > THR) ? THR : 0.f);
                *reinterpret_cast<float2*>(memrow + nn) = make_float2(n0v, n1v);
                char2 sp;
                sp.x = (n0v > THR) ? 1 : 0;
                sp.y = (n1v > THR) ? 1 : 0;
                *reinterpret_cast<char2*>(srow + nn) = sp;
            }
        }
    }
}

// ---------- int8 spike GEMM: CTA 128x128, 2 CTAs/SM, single chained acc ----------
// acc = ((S0)*128 + S1)*128 + S2 ; h = acc * 2^-23 recomposed exactly in epilogue.
template<int LAYER>
__global__ __launch_bounds__(256, 2) void gemm_i8(const float* __restrict__ bias) {
    constexpr int KDIM = (LAYER == 1) ? H2n : H1n;
    constexpr int NDIM = (LAYER == 1) ? H1n : H2n;
    constexpr bool SPK = (LAYER == 2);
    constexpr int KC = KDIM / 128;
    constexpr int NC = 3 * KC;

    extern __shared__ char smraw[];
    const uint32_t smbase = smem_u32(smraw);
    const uint32_t tb = (smbase + 1023u) & ~1023u;

    const int tid  = threadIdx.x;
    const int wid  = tid >> 5;
    const int lane = tid & 31;
    const int wm = wid >> 2;          // 0..1 (64 rows each)
    const int wn = wid & 3;           // 0..3 (32 cols each)
    const int m0  = blockIdx.y * 128;
    const int n0c = blockIdx.x * 128;

    const int8_t* A = (LAYER == 1) ? g_s2b : g_s1b;
    const int8_t* W[3];
    if (LAYER == 1) { W[0] = g_w1i0; W[1] = g_w1i1; W[2] = g_w1i2; }
    else            { W[0] = g_w2i0; W[1] = g_w2i1; W[2] = g_w2i2; }

    float* mem = (LAYER == 1) ? g_mem1 : g_mem2;
    int8_t* sout = (LAYER == 1) ? g_s1b : g_s2b;

    const int lrow = tid >> 3;          // 0..31
    const int lc16 = tid & 7;
    auto load_chunk = [&](int j) {
        const int p  = j / KC;
        const int kc = j - p * KC;
        const uint32_t sa = tb + (uint32_t)(j % 3) * I8_STAGE;
        const uint32_t sb = sa + I8_A;
        const int8_t* As = A + (size_t)m0 * KDIM + kc * 128 + lc16 * 16;
        const int8_t* Bs = W[p] + (size_t)n0c * KDIM + kc * 128 + lc16 * 16;
        #pragma unroll
        for (int q = 0; q < 4; q++) {
            int row = lrow + q * 32;
            uint32_t off = (uint32_t)row * 128 + (uint32_t)((lc16 ^ (row & 7)) << 4);
            cp16(sa + off, As + (size_t)row * KDIM);
            cp16(sb + off, Bs + (size_t)row * KDIM);
        }
        cp_commit();
    };

    const int aRow  = wm * 64 + (lane & 15);
    const uint32_t aXor = (uint32_t)(aRow & 7);
    uint32_t aob[4];
    #pragma unroll
    for (int f = 0; f < 4; f++) aob[f] = (uint32_t)(aRow + f * 16) * 128;
    const uint32_t aC16 = (uint32_t)(lane >> 4);
    const int bg     = lane >> 3;
    const int btile  = bg >> 1;
    const int bkhalf = bg & 1;
    const int bN     = wn * 32 + btile * 8 + (lane & 7);
    const uint32_t bXor = (uint32_t)(bN & 7);
    uint32_t bob[2];
    #pragma unroll
    for (int n2 = 0; n2 < 2; n2++) bob[n2] = (uint32_t)(bN + n2 * 16) * 128;

    int acc[4][4][4];
    #pragma unroll
    for (int f = 0; f < 4; f++)
        #pragma unroll
        for (int o = 0; o < 4; o++)
            #pragma unroll
            for (int q = 0; q < 4; q++) acc[f][o][q] = 0;

    load_chunk(0); load_chunk(1);

    for (int i = 0; i < NC; i++) {
        const int j = i + 2;
        if (j < NC) cp_wait1(); else cp_wait0();
        __syncthreads();
        if (j < NC) load_chunk(j);

        const uint32_t sa = tb + (uint32_t)(i % 3) * I8_STAGE;
        const uint32_t sb = sa + I8_A;
        #pragma unroll
        for (int ks = 0; ks < 4; ks++) {
            uint32_t af[4][4];
            #pragma unroll
            for (int f = 0; f < 4; f++) {
                uint32_t c16 = (uint32_t)(ks * 2) + aC16;
                ldsm4(af[f][0], af[f][1], af[f][2], af[f][3],
                      sa + aob[f] + ((c16 ^ aXor) << 4));
            }
            uint32_t bf[2][4];
            #pragma unroll
            for (int n2 = 0; n2 < 2; n2++) {
                uint32_t c16 = (uint32_t)(ks * 2 + bkhalf);
                ldsm4(bf[n2][0], bf[n2][1], bf[n2][2], bf[n2][3],
                      sb + bob[n2] + ((c16 ^ bXor) << 4));
            }
            #pragma unroll
            for (int f = 0; f < 4; f++)
                #pragma unroll
                for (int o = 0; o < 4; o++)
                    mma16832s8(acc[f][o], af[f], &bf[o >> 1][(o & 1) * 2]);
        }

        // shift-chain at pass boundaries: after pass 0 and pass 1
        if (i == KC - 1 || i == 2 * KC - 1) {
            #pragma unroll
            for (int f = 0; f < 4; f++)
                #pragma unroll
                for (int o = 0; o < 4; o++)
                    #pragma unroll
                    for (int q = 0; q < 4; q++) acc[f][o][q] *= 128;
        }
    }

    // epilogue: exact decomposition acc = 16384*q2 + 128*q1 + q0, q1,q0 in [0,128)
    const int r4  = lane >> 2;
    const int cp2 = (lane & 3) * 2;
    const int ncolw = n0c + wn * 32;
    #pragma unroll
    for (int f = 0; f < 4; f++) {
        #pragma unroll
        for (int h = 0; h < 2; h++) {
            const int m = m0 + wm * 64 + f * 16 + h * 8 + r4;
            float* memrow = mem + (size_t)m * NDIM + ncolw;
            int8_t* srow = sout + (size_t)m * NDIM + ncolw;
            float* spkrow = g_spk + (size_t)m * NDIM + ncolw;
            #pragma unroll
            for (int o = 0; o < 4; o++) {
                const int nn = o * 8 + cp2;
                float hv[2];
                #pragma unroll
                for (int q = 0; q < 2; q++) {
                    int v  = acc[f][o][2 * h + q];
                    int q2 = v >> 14;
                    int r  = v - (q2 << 14);
                    int q1 = r >> 7;
                    int q0 = r - (q1 << 7);
                    hv[q] = bias[ncolw + nn + q]
                          + (float)q2 * 0x1p-9f + (float)q1 * 0x1p-16f
                          + (float)q0 * 0x1p-23f;
                }
                float2 mv = *reinterpret_cast<float2*>(memrow + nn);
                float n0v = BETA * mv.x + hv[0] - ((mv.x > THR) ? THR : 0.f);
                float n1v = BETA * mv.y + hv[1] - ((mv.y > THR) ? THR : 0.f);
                *reinterpret_cast<float2*>(memrow + nn) = make_float2(n0v, n1v);
                char2 sp;
                sp.x = (n0v > THR) ? 1 : 0;
                sp.y = (n1v > THR) ? 1 : 0;
                *reinterpret_cast<char2*>(srow + nn) = sp;
                if (SPK) {
                    float2 pk = *reinterpret_cast<float2*>(spkrow + nn);
                    pk.x += (n0v > THR) ? 1.f : 0.f;
                    pk.y += (n1v > THR) ? 1.f : 0.f;
                    *reinterpret_cast<float2*>(spkrow + nn) = pk;
                }
            }
        }
    }
}

__global__ __launch_bounds__(256) void out_kernel(
    const float* __restrict__ Wo,
    const float* __restrict__ bo,
    float* __restrict__ out)
{
    __shared__ float wsh[64 * 129];
    const int tid = threadIdx.x;
    const int c  = tid & 63;
    const int b  = blockIdx.x * 4 + (tid >> 6);

    float acc = 0.f;
    for (int k0 = 0; k0 < H2n; k0 += 128) {
        __syncthreads();
        #pragma unroll
        for (int it = 0; it < 8; it++) {
            int l  = tid + it * 256;
            int c2 = l >> 5;
            int kk = (l & 31) * 4;
            float4 w4 = *reinterpret_cast<const float4*>(&Wo[(size_t)c2 * H2n + k0 + kk]);
            wsh[c2 * 129 + kk + 0] = w4.x;
            wsh[c2 * 129 + kk + 1] = w4.y;
            wsh[c2 * 129 + kk + 2] = w4.z;
            wsh[c2 * 129 + kk + 3] = w4.w;
        }
        __syncthreads();
        const float* sp = &g_spk[(size_t)b * H2n + k0];
        #pragma unroll
        for (int k = 0; k < 128; k += 4) {
            float4 s4 = *reinterpret_cast<const float4*>(sp + k);
            acc = fmaf(s4.x, wsh[c * 129 + k + 0], acc);
            acc = fmaf(s4.y, wsh[c * 129 + k + 1], acc);
            acc = fmaf(s4.z, wsh[c * 129 + k + 2], acc);
            acc = fmaf(s4.w, wsh[c * 129 + k + 3], acc);
        }
    }
    out[(size_t)b * Cn + c] = acc * (1.0f / NSTEPS) + bo[c];
}

extern "C" void kernel_launch(void* const* d_in, const int* in_sizes, int n_in,
                              void* d_out, int out_size)
{
    const float* x  = (const float*)d_in[0];
    const float* W1 = (const float*)d_in[1];
    const float* b1 = (const float*)d_in[2];
    const float* W2 = (const float*)d_in[3];
    const float* b2 = (const float*)d_in[4];
    const float* Wo = (const float*)d_in[5];
    const float* bo = (const float*)d_in[6];
    float* out = (float*)d_out;

    cudaFuncSetAttribute(gemm_t0, cudaFuncAttributeMaxDynamicSharedMemorySize, SMEM_T0);
    cudaFuncSetAttribute(gemm_i8<1>, cudaFuncAttributeMaxDynamicSharedMemorySize, SMEM_I8);
    cudaFuncSetAttribute(gemm_i8<2>, cudaFuncAttributeMaxDynamicSharedMemorySize, SMEM_I8);

    zero_kernel<<<512, 256>>>();
    split3_kernel<<<512, 256>>>(W1, (size_t)H1n * Dn, 0);
    split3_kernel<<<512, 256>>>(x,  (size_t)Bq * Dn, 1);
    split4_kernel<<<512, 256>>>(W1, (size_t)H1n * Dn, 0);
    split4_kernel<<<512, 256>>>(W2, (size_t)H2n * H1n, 1);

    dim3 gt0(H1n / 256, Bq / 128);              // (8, 32)
    dim3 g1(H1n / 128, Bq / 128);               // (16, 32) = 512 CTAs
    dim3 g2(H2n / 128, Bq / 128);               // (8, 32)  = 256 CTAs

    gemm_t0<<<gt0, 256, SMEM_T0>>>(b1);
    gemm_i8<2><<<g2, 256, SMEM_I8>>>(b2);
    for (int t = 1; t < NSTEPS; t++) {
        gemm_i8<1><<<g1, 256, SMEM_I8>>>(b1);
        gemm_i8<2><<<g2, 256, SMEM_I8>>>(b2);
    }
    out_kernel<<<Bq / 4, 256>>>(Wo, bo, out);
}

// round 15
// speedup vs baseline: 4.8550x; 1.0288x over previous
#include <cuda_runtime.h>
#include <cuda_bf16.h>
#include <cstdint>

#define DINL __device__ __forceinline__

namespace {
constexpr int Bq = 4096, Dn = 1024, H1n = 2048, H2n = 1024, Cn = 64, NSTEPS = 20;
constexpr float BETA = 0.9f, THR = 1.0f;
// int8 kernel: CTA 128x128, stage A(16K)+B(16K), 3-stage ring
constexpr int I8_A = 128 * 128, I8_B = 128 * 128;
constexpr int I8_STAGE = I8_A + I8_B;               // 32 KB
constexpr int SMEM_I8 = 3 * I8_STAGE + 1024;        // ~97 KB -> 2 CTAs/SM
}

__device__ float g_mem1[(size_t)Bq * H1n];
__device__ float g_mem2[(size_t)Bq * H2n];
__device__ float g_spk [(size_t)Bq * H2n];
__device__ int8_t g_s1b[(size_t)Bq * H1n];
__device__ int8_t g_s2b[(size_t)Bq * H2n];
// int8 3-window x splits (t0 only)
__device__ int8_t g_xj0[(size_t)Bq * Dn];
__device__ int8_t g_xj1[(size_t)Bq * Dn];
__device__ int8_t g_xj2[(size_t)Bq * Dn];
// int8 3-window weight splits
__device__ int8_t g_w1i0[(size_t)H1n * Dn];
__device__ int8_t g_w1i1[(size_t)H1n * Dn];
__device__ int8_t g_w1i2[(size_t)H1n * Dn];
__device__ int8_t g_w2i0[(size_t)H2n * H1n];
__device__ int8_t g_w2i1[(size_t)H2n * H1n];
__device__ int8_t g_w2i2[(size_t)H2n * H1n];

DINL uint32_t smem_u32(const void* p) {
    uint32_t a;
    asm("{ .reg .u64 t; cvta.to.shared.u64 t, %1; cvt.u32.u64 %0, t; }" : "=r"(a) : "l"(p));
    return a;
}
DINL void cp16(uint32_t dst, const void* src) {
    asm volatile("cp.async.cg.shared.global [%0], [%1], 16;" :: "r"(dst), "l"(src));
}
DINL void cp_commit() { asm volatile("cp.async.commit_group;" ::: "memory"); }
DINL void cp_wait1()  { asm volatile("cp.async.wait_group 1;" ::: "memory"); }
DINL void cp_wait0()  { asm volatile("cp.async.wait_group 0;" ::: "memory"); }
DINL void ldsm4(uint32_t& r0, uint32_t& r1, uint32_t& r2, uint32_t& r3, uint32_t addr) {
    asm volatile("ldmatrix.sync.aligned.m8n8.x4.shared.b16 {%0,%1,%2,%3}, [%4];"
                 : "=r"(r0), "=r"(r1), "=r"(r2), "=r"(r3) : "r"(addr));
}
DINL void mma16832s8(int* c, const uint32_t* a, const uint32_t* b) {
    asm volatile(
        "mma.sync.aligned.m16n8k32.row.col.s32.s8.s8.s32 "
        "{%0,%1,%2,%3},{%4,%5,%6,%7},{%8,%9},{%0,%1,%2,%3};"
        : "+r"(c[0]), "+r"(c[1]), "+r"(c[2]), "+r"(c[3])
        : "r"(a[0]), "r"(a[1]), "r"(a[2]), "r"(a[3]), "r"(b[0]), "r"(b[1]));
}

__global__ void zero_kernel() {
    size_t i = (size_t)blockIdx.x * blockDim.x + threadIdx.x;
    size_t stride = (size_t)gridDim.x * blockDim.x;
    const float4 z = make_float4(0.f, 0.f, 0.f, 0.f);
    for (size_t j = i; j < (size_t)Bq * H1n / 4; j += stride)
        reinterpret_cast<float4*>(g_mem1)[j] = z;
    for (size_t j = i; j < (size_t)Bq * H2n / 4; j += stride) {
        reinterpret_cast<float4*>(g_mem2)[j] = z;
        reinterpret_cast<float4*>(g_spk )[j] = z;
    }
}

// 3-window int8 split for weights: w = i0*2^-9 + i1*2^-16 + i2*2^-23
__global__ void split_w(const float* __restrict__ src, size_t n, int which) {
    int8_t *p0, *p1, *p2;
    if (which == 0) { p0 = g_w1i0; p1 = g_w1i1; p2 = g_w1i2; }
    else            { p0 = g_w2i0; p1 = g_w2i1; p2 = g_w2i2; }
    size_t i = (size_t)blockIdx.x * blockDim.x + threadIdx.x;
    size_t stride = (size_t)gridDim.x * blockDim.x;
    for (size_t j = i; j < n; j += stride) {
        float v = src[j];
        float t0 = fminf(fmaxf(rintf(v * 0x1p9f), -127.f), 127.f);
        float r  = v - t0 * 0x1p-9f;
        float t1 = fminf(fmaxf(rintf(r * 0x1p16f), -127.f), 127.f);
        r -= t1 * 0x1p-16f;
        float t2 = fminf(fmaxf(rintf(r * 0x1p23f), -127.f), 127.f);
        p0[j] = (int8_t)(int)t0;
        p1[j] = (int8_t)(int)t1;
        p2[j] = (int8_t)(int)t2;
    }
}

// 3-window int8 split for x: x = j0*2^-4 + j1*2^-11 + j2*2^-18 (+ residual <= 2^-19)
__global__ void split_x(const float* __restrict__ src, size_t n) {
    size_t i = (size_t)blockIdx.x * blockDim.x + threadIdx.x;
    size_t stride = (size_t)gridDim.x * blockDim.x;
    for (size_t j = i; j < n; j += stride) {
        float v = src[j];
        float t0 = fminf(fmaxf(rintf(v * 0x1p4f), -127.f), 127.f);
        float r  = v - t0 * 0x1p-4f;
        float t1 = fminf(fmaxf(rintf(r * 0x1p11f), -127.f), 127.f);
        r -= t1 * 0x1p-11f;
        float t2 = fminf(fmaxf(rintf(r * 0x1p18f), -127.f), 127.f);
        g_xj0[j] = (int8_t)(int)t0;
        g_xj1[j] = (int8_t)(int)t1;
        g_xj2[j] = (int8_t)(int)t2;
    }
}

// ---------- int8 GEMM + fused LIF, CTA 128x128, 2 CTAs/SM, chained acc ----------
// LAYER 0: t0 layer-1 (A = x windows, 6 passes, scales 2^-13/2^-20/2^-27)
// LAYER 1: layer-1    (A = s2 spikes, 3 passes, scales 2^-9/2^-16/2^-23)
// LAYER 2: layer-2    (A = s1 spikes, 3 passes, + spike-sum accumulation)
template<int LAYER>
__global__ __launch_bounds__(256, 2) void gemm_i8(const float* __restrict__ bias) {
    constexpr int KDIM = (LAYER == 2) ? H1n : ((LAYER == 1) ? H2n : Dn);
    constexpr int NDIM = (LAYER == 2) ? H2n : H1n;
    constexpr bool SPK = (LAYER == 2);
    constexpr int KC = KDIM / 128;
    constexpr int NPASS = (LAYER == 0) ? 6 : 3;
    constexpr int NC = NPASS * KC;
    // chain boundaries (multiply acc by 128 after these chunk indices)
    constexpr int CB1 = (LAYER == 0) ? (1 * KC - 1) : (1 * KC - 1);
    constexpr int CB2 = (LAYER == 0) ? (3 * KC - 1) : (2 * KC - 1);

    extern __shared__ char smraw[];
    const uint32_t smbase = smem_u32(smraw);
    const uint32_t tb = (smbase + 1023u) & ~1023u;

    const int tid  = threadIdx.x;
    const int wid  = tid >> 5;
    const int lane = tid & 31;
    const int wm = wid >> 2;          // 0..1 (64 rows each)
    const int wn = wid & 3;           // 0..3 (32 cols each)
    const int m0  = blockIdx.y * 128;
    const int n0c = blockIdx.x * 128;

    const int8_t* Ap[NPASS];
    const int8_t* Bp[NPASS];
    if (LAYER == 0) {
        // G0={j0*i0}; G1={j0*i1, j1*i0}; G2={j0*i2, j1*i1, j2*i0}
        Ap[0] = g_xj0; Bp[0] = g_w1i0;
        Ap[1] = g_xj0; Bp[1] = g_w1i1;
        Ap[2] = g_xj1; Bp[2] = g_w1i0;
        Ap[3] = g_xj0; Bp[3] = g_w1i2;
        Ap[4] = g_xj1; Bp[4] = g_w1i1;
        Ap[5] = g_xj2; Bp[5] = g_w1i0;
    } else if (LAYER == 1) {
        Ap[0] = g_s2b; Bp[0] = g_w1i0;
        Ap[1] = g_s2b; Bp[1] = g_w1i1;
        Ap[2] = g_s2b; Bp[2] = g_w1i2;
    } else {
        Ap[0] = g_s1b; Bp[0] = g_w2i0;
        Ap[1] = g_s1b; Bp[1] = g_w2i1;
        Ap[2] = g_s1b; Bp[2] = g_w2i2;
    }

    float* mem = (LAYER == 2) ? g_mem2 : g_mem1;
    int8_t* sout = (LAYER == 2) ? g_s2b : g_s1b;

    const int lrow = tid >> 3;          // 0..31
    const int lc16 = tid & 7;
    auto load_chunk = [&](int j) {
        const int p  = j / KC;
        const int kc = j - p * KC;
        const uint32_t sa = tb + (uint32_t)(j % 3) * I8_STAGE;
        const uint32_t sb = sa + I8_A;
        const int8_t* As = Ap[p] + (size_t)m0 * KDIM + kc * 128 + lc16 * 16;
        const int8_t* Bs = Bp[p] + (size_t)n0c * KDIM + kc * 128 + lc16 * 16;
        #pragma unroll
        for (int q = 0; q < 4; q++) {
            int row = lrow + q * 32;
            uint32_t off = (uint32_t)row * 128 + (uint32_t)((lc16 ^ (row & 7)) << 4);
            cp16(sa + off, As + (size_t)row * KDIM);
            cp16(sb + off, Bs + (size_t)row * KDIM);
        }
        cp_commit();
    };

    const int aRow  = wm * 64 + (lane & 15);
    const uint32_t aXor = (uint32_t)(aRow & 7);
    uint32_t aob[4];
    #pragma unroll
    for (int f = 0; f < 4; f++) aob[f] = (uint32_t)(aRow + f * 16) * 128;
    const uint32_t aC16 = (uint32_t)(lane >> 4);
    const int bg     = lane >> 3;
    const int btile  = bg >> 1;
    const int bkhalf = bg & 1;
    const int bN     = wn * 32 + btile * 8 + (lane & 7);
    const uint32_t bXor = (uint32_t)(bN & 7);
    uint32_t bob[2];
    #pragma unroll
    for (int n2 = 0; n2 < 2; n2++) bob[n2] = (uint32_t)(bN + n2 * 16) * 128;

    int acc[4][4][4];
    #pragma unroll
    for (int f = 0; f < 4; f++)
        #pragma unroll
        for (int o = 0; o < 4; o++)
            #pragma unroll
            for (int q = 0; q < 4; q++) acc[f][o][q] = 0;

    load_chunk(0); load_chunk(1);

    for (int i = 0; i < NC; i++) {
        const int j = i + 2;
        if (j < NC) cp_wait1(); else cp_wait0();
        __syncthreads();
        if (j < NC) load_chunk(j);

        const uint32_t sa = tb + (uint32_t)(i % 3) * I8_STAGE;
        const uint32_t sb = sa + I8_A;
        #pragma unroll
        for (int ks = 0; ks < 4; ks++) {
            uint32_t af[4][4];
            #pragma unroll
            for (int f = 0; f < 4; f++) {
                uint32_t c16 = (uint32_t)(ks * 2) + aC16;
                ldsm4(af[f][0], af[f][1], af[f][2], af[f][3],
                      sa + aob[f] + ((c16 ^ aXor) << 4));
            }
            uint32_t bf[2][4];
            #pragma unroll
            for (int n2 = 0; n2 < 2; n2++) {
                uint32_t c16 = (uint32_t)(ks * 2 + bkhalf);
                ldsm4(bf[n2][0], bf[n2][1], bf[n2][2], bf[n2][3],
                      sb + bob[n2] + ((c16 ^ bXor) << 4));
            }
            #pragma unroll
            for (int f = 0; f < 4; f++)
                #pragma unroll
                for (int o = 0; o < 4; o++)
                    mma16832s8(acc[f][o], af[f], &bf[o >> 1][(o & 1) * 2]);
        }

        if (i == CB1 || i == CB2) {
            #pragma unroll
            for (int f = 0; f < 4; f++)
                #pragma unroll
                for (int o = 0; o < 4; o++)
                    #pragma unroll
                    for (int q = 0; q < 4; q++) acc[f][o][q] *= 128;
        }
    }

    // epilogue: exact decomposition acc = 16384*q2 + 128*q1 + q0, q1,q0 in [0,128)
    const float S2 = (LAYER == 0) ? 0x1p-13f : 0x1p-9f;
    const float S1 = (LAYER == 0) ? 0x1p-20f : 0x1p-16f;
    const float S0 = (LAYER == 0) ? 0x1p-27f : 0x1p-23f;
    const int r4  = lane >> 2;
    const int cp2 = (lane & 3) * 2;
    const int ncolw = n0c + wn * 32;
    #pragma unroll
    for (int f = 0; f < 4; f++) {
        #pragma unroll
        for (int h = 0; h < 2; h++) {
            const int m = m0 + wm * 64 + f * 16 + h * 8 + r4;
            float* memrow = mem + (size_t)m * NDIM + ncolw;
            int8_t* srow = sout + (size_t)m * NDIM + ncolw;
            float* spkrow = g_spk + (size_t)m * NDIM + ncolw;
            #pragma unroll
            for (int o = 0; o < 4; o++) {
                const int nn = o * 8 + cp2;
                float hv[2];
                #pragma unroll
                for (int q = 0; q < 2; q++) {
                    int v  = acc[f][o][2 * h + q];
                    int q2 = v >> 14;
                    int r  = v - (q2 << 14);
                    int q1 = r >> 7;
                    int q0 = r - (q1 << 7);
                    hv[q] = bias[ncolw + nn + q]
                          + (float)q2 * S2 + (float)q1 * S1 + (float)q0 * S0;
                }
                float2 mv = *reinterpret_cast<float2*>(memrow + nn);
                float n0v = BETA * mv.x + hv[0] - ((mv.x > THR) ? THR : 0.f);
                float n1v = BETA * mv.y + hv[1] - ((mv.y > THR) ? THR : 0.f);
                *reinterpret_cast<float2*>(memrow + nn) = make_float2(n0v, n1v);
                char2 sp;
                sp.x = (n0v > THR) ? 1 : 0;
                sp.y = (n1v > THR) ? 1 : 0;
                *reinterpret_cast<char2*>(srow + nn) = sp;
                if (SPK) {
                    float2 pk = *reinterpret_cast<float2*>(spkrow + nn);
                    pk.x += (n0v > THR) ? 1.f : 0.f;
                    pk.y += (n1v > THR) ? 1.f : 0.f;
                    *reinterpret_cast<float2*>(spkrow + nn) = pk;
                }
            }
        }
    }
}

__global__ __launch_bounds__(256) void out_kernel(
    const float* __restrict__ Wo,
    const float* __restrict__ bo,
    float* __restrict__ out)
{
    __shared__ float wsh[64 * 129];
    const int tid = threadIdx.x;
    const int c  = tid & 63;
    const int b  = blockIdx.x * 4 + (tid >> 6);

    float acc = 0.f;
    for (int k0 = 0; k0 < H2n; k0 += 128) {
        __syncthreads();
        #pragma unroll
        for (int it = 0; it < 8; it++) {
            int l  = tid + it * 256;
            int c2 = l >> 5;
            int kk = (l & 31) * 4;
            float4 w4 = *reinterpret_cast<const float4*>(&Wo[(size_t)c2 * H2n + k0 + kk]);
            wsh[c2 * 129 + kk + 0] = w4.x;
            wsh[c2 * 129 + kk + 1] = w4.y;
            wsh[c2 * 129 + kk + 2] = w4.z;
            wsh[c2 * 129 + kk + 3] = w4.w;
        }
        __syncthreads();
        const float* sp = &g_spk[(size_t)b * H2n + k0];
        #pragma unroll
        for (int k = 0; k < 128; k += 4) {
            float4 s4 = *reinterpret_cast<const float4*>(sp + k);
            acc = fmaf(s4.x, wsh[c * 129 + k + 0], acc);
            acc = fmaf(s4.y, wsh[c * 129 + k + 1], acc);
            acc = fmaf(s4.z, wsh[c * 129 + k + 2], acc);
            acc = fmaf(s4.w, wsh[c * 129 + k + 3], acc);
        }
    }
    out[(size_t)b * Cn + c] = acc * (1.0f / NSTEPS) + bo[c];
}

extern "C" void kernel_launch(void* const* d_in, const int* in_sizes, int n_in,
                              void* d_out, int out_size)
{
    const float* x  = (const float*)d_in[0];
    const float* W1 = (const float*)d_in[1];
    const float* b1 = (const float*)d_in[2];
    const float* W2 = (const float*)d_in[3];
    const float* b2 = (const float*)d_in[4];
    const float* Wo = (const float*)d_in[5];
    const float* bo = (const float*)d_in[6];
    float* out = (float*)d_out;

    cudaFuncSetAttribute(gemm_i8<0>, cudaFuncAttributeMaxDynamicSharedMemorySize, SMEM_I8);
    cudaFuncSetAttribute(gemm_i8<1>, cudaFuncAttributeMaxDynamicSharedMemorySize, SMEM_I8);
    cudaFuncSetAttribute(gemm_i8<2>, cudaFuncAttributeMaxDynamicSharedMemorySize, SMEM_I8);

    zero_kernel<<<512, 256>>>();
    split_w<<<512, 256>>>(W1, (size_t)H1n * Dn, 0);
    split_w<<<512, 256>>>(W2, (size_t)H2n * H1n, 1);
    split_x<<<256, 256>>>(x, (size_t)Bq * Dn);

    dim3 g1(H1n / 128, Bq / 128);               // (16, 32) = 512 CTAs
    dim3 g2(H2n / 128, Bq / 128);               // (8, 32)  = 256 CTAs

    gemm_i8<0><<<g1, 256, SMEM_I8>>>(b1);
    gemm_i8<2><<<g2, 256, SMEM_I8>>>(b2);
    for (int t = 1; t < NSTEPS; t++) {
        gemm_i8<1><<<g1, 256, SMEM_I8>>>(b1);
        gemm_i8<2><<<g2, 256, SMEM_I8>>>(b2);
    }
    out_kernel<<<Bq / 4, 256>>>(Wo, bo, out);
}